// round 12
// baseline (speedup 1.0000x reference)
#include <cuda_runtime.h>
#include <cuda_fp16.h>
#include <math.h>
#include <stdint.h>

#define BB 4
#define NN 4096
#define DD 256
#define MTOT (BB*NN)          // 16384
#define KAUG 768              // B-side 3-term split width
#define AW   512              // A-side [h|l] width
#define SCALE_F 0.17677669529663689f
#define BAND 4.0e-3f

// ---------------- static device scratch ------------------------------------
__device__ __half g_Aaug[(size_t)MTOT*AW];     // x augmented [h|l]
__device__ __half g_yh  [(size_t)MTOT*DD];     // y rounded to fp16 (attn K)
__device__ float  g_Qm  [(size_t)MTOT*DD];     // x . (Wq Wk^T)
__device__ float  g_VP  [(size_t)MTOT*DD];     // x . (Wv Wp)
__device__ __half g_Wt2 [(size_t)2*DD*KAUG];   // [M ; Wvp] split B-style, 512x768
__device__ int    g_cnt;
__device__ int    g_list[MTOT];
__device__ float  g_mval[MTOT];
__device__ double g_sumacc[MTOT];
__device__ unsigned long long g_maxp[MTOT];

// ---------------- PTX helpers ----------------------------------------------
__device__ __forceinline__ uint32_t smem_u32(const void* p){
    uint32_t a;
    asm("{ .reg .u64 t; cvta.to.shared.u64 t, %1; cvt.u32.u64 %0, t; }" : "=r"(a) : "l"(p));
    return a;
}
#define CP16(dst, src) \
    asm volatile("cp.async.cg.shared.global [%0], [%1], 16;" :: "r"(dst), "l"(src) : "memory")
#define CPC()  asm volatile("cp.async.commit_group;" ::: "memory")
#define CPW0() asm volatile("cp.async.wait_group 0;" ::: "memory")
#define CPW2() asm volatile("cp.async.wait_group 2;" ::: "memory")

__device__ __forceinline__ void ldsm4(uint32_t a, uint32_t& r0, uint32_t& r1,
                                      uint32_t& r2, uint32_t& r3){
    asm volatile("ldmatrix.sync.aligned.m8n8.x4.shared.b16 {%0,%1,%2,%3}, [%4];"
        : "=r"(r0), "=r"(r1), "=r"(r2), "=r"(r3) : "r"(a));
}
__device__ __forceinline__ void mma16816(float* c,
        uint32_t a0, uint32_t a1, uint32_t a2, uint32_t a3,
        uint32_t b0, uint32_t b1){
    asm volatile("mma.sync.aligned.m16n8k16.row.col.f32.f16.f16.f32 "
        "{%0,%1,%2,%3}, {%4,%5,%6,%7}, {%8,%9}, {%0,%1,%2,%3};"
        : "+f"(c[0]), "+f"(c[1]), "+f"(c[2]), "+f"(c[3])
        : "r"(a0), "r"(a1), "r"(a2), "r"(a3), "r"(b0), "r"(b1));
}

// ---------------- fused input prep: x -> Aaug [h|l], y -> fp16 --------------
__global__ void prep_xy(const float* __restrict__ x, const float* __restrict__ y,
                        __half* __restrict__ Aaug, __half* __restrict__ yh)
{
    const size_t totalx = (size_t)MTOT * 64;
    const size_t total  = totalx * 2;
    for (size_t i = (size_t)blockIdx.x*blockDim.x + threadIdx.x; i < total;
         i += (size_t)gridDim.x*blockDim.x) {
        if (i < totalx) {
            size_t row = i >> 6; int c4 = (int)(i & 63);
            float4 v = ((const float4*)x)[i];
            __half h0=__float2half_rn(v.x), h1=__float2half_rn(v.y);
            __half h2=__float2half_rn(v.z), h3=__float2half_rn(v.w);
            __half2 H01=__halves2half2(h0,h1), H23=__halves2half2(h2,h3);
            __half2 L01=__halves2half2(__float2half_rn(v.x-__half2float(h0)),
                                       __float2half_rn(v.y-__half2float(h1)));
            __half2 L23=__halves2half2(__float2half_rn(v.z-__half2float(h2)),
                                       __float2half_rn(v.w-__half2float(h3)));
            __half* base = Aaug + row*AW + c4*4;
            ((__half2*)base)[0] = H01; ((__half2*)base)[1] = H23;
            ((__half2*)(base+256))[0] = L01; ((__half2*)(base+256))[1] = L23;
        } else {
            size_t j = i - totalx;
            float4 v = ((const float4*)y)[j];
            ((__half2*)yh)[j*2]   = __halves2half2(__float2half_rn(v.x), __float2half_rn(v.y));
            ((__half2*)yh)[j*2+1] = __halves2half2(__float2half_rn(v.z), __float2half_rn(v.w));
        }
    }
}

// ---------------- weight GEMMs with split epilogue --------------------------
// M = Wq @ Wk^T ; split [h|l|h] written to Wt2 rows [0,256)
__global__ __launch_bounds__(256) void wgemm_qk(const float* __restrict__ Wq,
                                                const float* __restrict__ Wk,
                                                __half* __restrict__ Wt2)
{
    __shared__ float As[64][17];
    __shared__ float Ws[16][64];
    const int t  = threadIdx.x;
    const int tx = t & 15, ty = t >> 4;
    const int m0 = blockIdx.x * 64, n0 = blockIdx.y * 64;
    const int lr = t >> 2, lc = (t & 3) * 4;
    float acc[4][4] = {};
    for (int kk = 0; kk < 256; kk += 16) {
        float4 av = *(const float4*)(Wq + (size_t)(m0 + lr) * 256 + kk + lc);
        As[lr][lc+0]=av.x; As[lr][lc+1]=av.y; As[lr][lc+2]=av.z; As[lr][lc+3]=av.w;
        #pragma unroll
        for (int i = 0; i < 4; i++)
            Ws[ty][tx*4+i] = Wk[(size_t)(n0 + tx*4 + i) * 256 + kk + ty];
        __syncthreads();
        #pragma unroll
        for (int c = 0; c < 16; c++) {
            float a0=As[ty*4+0][c], a1=As[ty*4+1][c], a2=As[ty*4+2][c], a3=As[ty*4+3][c];
            float4 w = *(const float4*)&Ws[c][tx*4];
            acc[0][0]+=a0*w.x; acc[0][1]+=a0*w.y; acc[0][2]+=a0*w.z; acc[0][3]+=a0*w.w;
            acc[1][0]+=a1*w.x; acc[1][1]+=a1*w.y; acc[1][2]+=a1*w.z; acc[1][3]+=a1*w.w;
            acc[2][0]+=a2*w.x; acc[2][1]+=a2*w.y; acc[2][2]+=a2*w.z; acc[2][3]+=a2*w.w;
            acc[3][0]+=a3*w.x; acc[3][1]+=a3*w.y; acc[3][2]+=a3*w.z; acc[3][3]+=a3*w.w;
        }
        __syncthreads();
    }
    #pragma unroll
    for (int j2 = 0; j2 < 4; j2++) {
        int i = m0 + ty*4 + j2;
        #pragma unroll
        for (int c = 0; c < 4; c++) {
            int n = n0 + tx*4 + c;
            float v = acc[j2][c];
            __half h = __float2half_rn(v);
            __half l = __float2half_rn(v - __half2float(h));
            __half* dst = Wt2 + (size_t)n*KAUG;
            dst[i] = h; dst[256 + i] = l; dst[512 + i] = h;
        }
    }
}

// Wvp = Wv @ Wp ; split [h|l|h] written to Wt2 rows [256,512)
__global__ __launch_bounds__(256) void wgemm_vp(const float* __restrict__ Wv,
                                                const float* __restrict__ Wp,
                                                __half* __restrict__ Wt2)
{
    __shared__ float As[64][17];
    __shared__ float Ws[16][64];
    const int t  = threadIdx.x;
    const int tx = t & 15, ty = t >> 4;
    const int m0 = blockIdx.x * 64, n0 = blockIdx.y * 64;
    const int lr = t >> 2, lc = (t & 3) * 4;
    float acc[4][4] = {};
    for (int kk = 0; kk < 256; kk += 16) {
        float4 av = *(const float4*)(Wv + (size_t)(m0 + lr) * 256 + kk + lc);
        As[lr][lc+0]=av.x; As[lr][lc+1]=av.y; As[lr][lc+2]=av.z; As[lr][lc+3]=av.w;
        float4 wv = *(const float4*)(Wp + (size_t)(kk + ty) * 256 + n0 + tx * 4);
        *(float4*)&Ws[ty][tx*4] = wv;
        __syncthreads();
        #pragma unroll
        for (int c = 0; c < 16; c++) {
            float a0=As[ty*4+0][c], a1=As[ty*4+1][c], a2=As[ty*4+2][c], a3=As[ty*4+3][c];
            float4 w = *(const float4*)&Ws[c][tx*4];
            acc[0][0]+=a0*w.x; acc[0][1]+=a0*w.y; acc[0][2]+=a0*w.z; acc[0][3]+=a0*w.w;
            acc[1][0]+=a1*w.x; acc[1][1]+=a1*w.y; acc[1][2]+=a1*w.z; acc[1][3]+=a1*w.w;
            acc[2][0]+=a2*w.x; acc[2][1]+=a2*w.y; acc[2][2]+=a2*w.z; acc[2][3]+=a2*w.w;
            acc[3][0]+=a3*w.x; acc[3][1]+=a3*w.y; acc[3][2]+=a3*w.z; acc[3][3]+=a3*w.w;
        }
        __syncthreads();
    }
    #pragma unroll
    for (int j2 = 0; j2 < 4; j2++) {
        int i = m0 + ty*4 + j2;
        #pragma unroll
        for (int c = 0; c < 4; c++) {
            int n = n0 + tx*4 + c;
            float v = acc[j2][c];
            __half h = __float2half_rn(v);
            __half l = __float2half_rn(v - __half2float(h));
            __half* dst = Wt2 + (size_t)(256 + n)*KAUG;
            dst[i] = h; dst[256 + i] = l; dst[512 + i] = h;
        }
    }
}

// ---------------- fused HMMA GEMM: [Qm | VP] = Aaug . Wt2^T -----------------
// CTA tile m128 x n256, warps 2(m) x 4(n), m64n64 per warp. A is 512-wide
// [h|l]: chunks 0-7 -> Ah x Bh, 8-15 -> Ah x Bl, 16-23 -> Al x Bh.
#define HG_A0 0
#define HG_B0 20480               // 2 x 10240 A bufs
#define HG_SM (HG_B0 + 2*20480)   // 61440

__global__ __launch_bounds__(256) void hgemm2(const __half* __restrict__ A,
                                              const __half* __restrict__ Bw,
                                              float* __restrict__ Qm,
                                              float* __restrict__ VP)
{
    __shared__ __align__(16) char sm[HG_SM];
    const uint32_t sb = smem_u32(sm);
    const int t = threadIdx.x, lane = t & 31, wid = t >> 5;
    const int wm = wid >> 2, wn = wid & 3;
    const int m0 = blockIdx.x * 128;
    const int brow0 = blockIdx.y * 256;
    float* C = blockIdx.y ? VP : Qm;

    float c[4][8][4] = {};

    // prologue: chunk 0
    {
        #pragma unroll
        for (int i = 0; i < 2; i++) {
            int sidx = t*2 + i; int row = sidx >> 2, seg = sidx & 3;
            CP16(sb + HG_A0 + row*80 + seg*16, A + (size_t)(m0+row)*AW + seg*8);
        }
        #pragma unroll
        for (int i = 0; i < 4; i++) {
            int sidx = t*4 + i; int row = sidx >> 2, seg = sidx & 3;
            CP16(sb + HG_B0 + row*80 + seg*16, Bw + (size_t)(brow0+row)*KAUG + seg*8);
        }
        CPC();
    }
    const uint32_t aRowOff = (uint32_t)(wm*64 + (lane&15))*80 + ((lane>>4)&1)*16;
    const uint32_t bRowOff = (uint32_t)(wn*64 + (lane&7) + ((lane>>3)&1)*8)*80
                           + ((lane>>4)&1)*16;

    for (int ch = 0; ch < 24; ch++) {
        int buf = ch & 1;
        CPW0();
        __syncthreads();
        if (ch + 1 < 24) {
            int nc = ch + 1, nb = nc & 1;
            int ak = ((nc < 16) ? (nc & 7) : (nc - 8)) * 32;
            int bk = nc * 32;
            #pragma unroll
            for (int i = 0; i < 2; i++) {
                int sidx = t*2 + i; int row = sidx >> 2, seg = sidx & 3;
                CP16(sb + HG_A0 + nb*10240 + row*80 + seg*16,
                     A + (size_t)(m0+row)*AW + ak + seg*8);
            }
            #pragma unroll
            for (int i = 0; i < 4; i++) {
                int sidx = t*4 + i; int row = sidx >> 2, seg = sidx & 3;
                CP16(sb + HG_B0 + nb*20480 + row*80 + seg*16,
                     Bw + (size_t)(brow0+row)*KAUG + bk + seg*8);
            }
            CPC();
        }
        uint32_t aBase = sb + HG_A0 + buf*10240 + aRowOff;
        uint32_t bBase = sb + HG_B0 + buf*20480 + bRowOff;
        #pragma unroll
        for (int ks = 0; ks < 2; ks++) {
            uint32_t a[4][4];
            #pragma unroll
            for (int mi = 0; mi < 4; mi++)
                ldsm4(aBase + mi*(16*80) + ks*32, a[mi][0], a[mi][1], a[mi][2], a[mi][3]);
            #pragma unroll
            for (int p = 0; p < 4; p++) {
                uint32_t b0,b1,b2,b3;
                ldsm4(bBase + p*1280 + ks*32, b0,b1,b2,b3);
                #pragma unroll
                for (int mi = 0; mi < 4; mi++) {
                    mma16816(c[mi][2*p+0], a[mi][0],a[mi][1],a[mi][2],a[mi][3], b0,b2);
                    mma16816(c[mi][2*p+1], a[mi][0],a[mi][1],a[mi][2],a[mi][3], b1,b3);
                }
            }
        }
    }
    #pragma unroll
    for (int mi = 0; mi < 4; mi++)
        #pragma unroll
        for (int ni = 0; ni < 8; ni++) {
            int row = m0 + wm*64 + mi*16 + (lane>>2);
            int col = wn*64 + ni*8 + 2*(lane&3);
            *(float2*)(C + (size_t)row*DD + col) =
                make_float2(c[mi][ni][0], c[mi][ni][1]);
            *(float2*)(C + (size_t)(row+8)*DD + col) =
                make_float2(c[mi][ni][2], c[mi][ni][3]);
        }
}

// ---------------- 1-term attention, m64n64 warp tiles, key-tile 256 ---------
#define AQ_STRIDE  528                         // 256 half + 16B pad
#define AQS        (128*AQ_STRIDE)             // 67584
#define KB_OFF     AQS
#define KST        (256*144)                   // 64-dim chunk, 256 keys
#define MRG        (KB_OFF + 4*KST)            // 215040
#define SMEM_ATTN  (MRG + 8192)                // 223232

__global__ __launch_bounds__(256) void attn2(const float* __restrict__ Qm_,
        const __half* __restrict__ yh_, const float* __restrict__ VP_,
        const float* __restrict__ bp, float* __restrict__ Og_)
{
    extern __shared__ __align__(128) char smem[];
    const uint32_t sb = smem_u32(smem);
    const int t = threadIdx.x, lane = t & 31, wid = t >> 5;
    const int wm = wid >> 2, wn = wid & 3;
    const int b = blockIdx.y, q0 = blockIdx.x * 128;

    const __half* Kb = yh_ + (size_t)b*NN*DD;

    // prologue: 3 chunks (kt=0, dim-chunks 0..2)
    #pragma unroll
    for (int st = 0; st < 3; st++) {
        #pragma unroll
        for (int i = 0; i < 8; i++) {
            int sidx = t*8 + i; int row = sidx >> 3, seg = sidx & 7;
            CP16(sb + KB_OFF + st*KST + row*144 + seg*16,
                 Kb + (size_t)row*DD + st*64 + seg*8);
        }
        CPC();
    }

    float* bp_s = (float*)(smem + MRG + 7168);   // 256 floats
    if (t < 64) ((float4*)bp_s)[t] = ((const float4*)bp)[t];

    // build Qh tile (pre-scaled, rounded to fp16)
    const float* Qg = Qm_ + (size_t)(b*NN + q0)*DD;
    #pragma unroll 4
    for (int i = 0; i < 32; i++) {
        int e4 = t + i*256;
        int row = e4 >> 6, c4 = e4 & 63;
        float4 v = ((const float4*)Qg)[(size_t)row*64 + c4];
        __half2 H01 = __halves2half2(__float2half_rn(v.x*SCALE_F),
                                     __float2half_rn(v.y*SCALE_F));
        __half2 H23 = __halves2half2(__float2half_rn(v.z*SCALE_F),
                                     __float2half_rn(v.w*SCALE_F));
        char* base = smem + (size_t)row*AQ_STRIDE + (size_t)c4*8;
        *(__half2*)(base)   = H01;
        *(__half2*)(base+4) = H23;
    }

    float c[4][8][4] = {};
    float rm[8], rs[8]; int ra[8];
    #pragma unroll
    for (int j = 0; j < 8; j++) { rm[j] = -3.0e38f; rs[j] = 0.f; ra[j] = 0; }

    const uint32_t aRowOff = (uint32_t)(wm*64 + (lane&15))*AQ_STRIDE + ((lane>>4)&1)*16;
    const uint32_t bRowOff = (uint32_t)(wn*64 + (lane&7) + ((lane>>3)&1)*8)*144
                           + ((lane>>4)&1)*16;

    for (int idx = 0; idx < 64; idx++) {
        CPW2();                        // chunk idx resident
        __syncthreads();
        if (idx + 3 < 64) {
            int nx = idx + 3, nkt = nx >> 2, nch = nx & 3, nb = nx & 3;
            #pragma unroll
            for (int i = 0; i < 8; i++) {
                int sidx = t*8 + i; int row = sidx >> 3, seg = sidx & 7;
                CP16(sb + KB_OFF + nb*KST + row*144 + seg*16,
                     Kb + (size_t)(nkt*256+row)*DD + nch*64 + seg*8);
            }
            CPC();
        }
        uint32_t aBase = sb + aRowOff + (uint32_t)(idx & 3)*128;
        uint32_t bBase = sb + KB_OFF + (idx & 3)*KST + bRowOff;
        #pragma unroll
        for (int ks = 0; ks < 4; ks++) {
            uint32_t a[4][4];
            #pragma unroll
            for (int mi = 0; mi < 4; mi++)
                ldsm4(aBase + mi*(16*AQ_STRIDE) + ks*32,
                      a[mi][0], a[mi][1], a[mi][2], a[mi][3]);
            #pragma unroll
            for (int p = 0; p < 4; p++) {
                uint32_t b0,b1,b2,b3;
                ldsm4(bBase + p*2304 + ks*32, b0,b1,b2,b3);
                #pragma unroll
                for (int mi = 0; mi < 4; mi++) {
                    mma16816(c[mi][2*p+0], a[mi][0],a[mi][1],a[mi][2],a[mi][3], b0,b2);
                    mma16816(c[mi][2*p+1], a[mi][0],a[mi][1],a[mi][2],a[mi][3], b1,b3);
                }
            }
        }

        if ((idx & 3) == 3) {
            int kt = idx >> 2;
            #pragma unroll
            for (int j = 0; j < 8; j++) {
                int mi = j >> 1, hr = (j & 1) * 2;
                float tm = -3.0e38f; int ta = 0;
                #pragma unroll
                for (int ni = 0; ni < 8; ni++) {
                    float v0 = c[mi][ni][hr], v1 = c[mi][ni][hr+1];
                    int col = ni*8 + 2*(lane&3);
                    if (v0 > tm) { tm = v0; ta = col; }
                    if (v1 > tm) { tm = v1; ta = col+1; }
                }
                #pragma unroll
                for (int off = 1; off <= 2; off <<= 1) {
                    float om = __shfl_xor_sync(0xffffffffu, tm, off);
                    int   oa = __shfl_xor_sync(0xffffffffu, ta, off);
                    if (om > tm || (om == tm && oa < ta)) { tm = om; ta = oa; }
                }
                float ts = 0.f;
                #pragma unroll
                for (int ni = 0; ni < 8; ni++) {
                    ts += __expf(c[mi][ni][hr]   - tm);
                    ts += __expf(c[mi][ni][hr+1] - tm);
                }
                #pragma unroll
                for (int off = 1; off <= 2; off <<= 1)
                    ts += __shfl_xor_sync(0xffffffffu, ts, off);
                if (tm > rm[j]) {
                    rs[j] = rs[j]*__expf(rm[j]-tm) + ts;
                    rm[j] = tm;
                    ra[j] = kt*256 + wn*64 + ta;
                } else {
                    rs[j] += ts*__expf(tm - rm[j]);
                }
            }
            #pragma unroll
            for (int mi = 0; mi < 4; mi++)
                #pragma unroll
                for (int ni = 0; ni < 8; ni++)
                    #pragma unroll
                    for (int r = 0; r < 4; r++) c[mi][ni][r] = 0.f;
        }
    }

    // ---- merge 4 n-segments, classify, write ----
    float* m_arr = (float*)(smem + MRG);            // [4][128]
    float* s_arr = (float*)(smem + MRG + 2048);     // [4][128]
    int*   a_arr = (int*)  (smem + MRG + 4096);     // [4][128]
    float* p_arr = (float*)(smem + MRG + 6144);     // [128]
    int*   f_arr = (int*)  (smem + MRG + 6656);     // [128]
    if ((lane & 3) == 0) {
        #pragma unroll
        for (int j = 0; j < 8; j++) {
            int row = wm*64 + (j>>1)*16 + (j&1)*8 + (lane>>2);
            m_arr[wn*128 + row] = rm[j];
            s_arr[wn*128 + row] = rs[j];
            a_arr[wn*128 + row] = ra[j];
        }
    }
    __syncthreads();
    if (t < 128) {
        float mm = m_arr[t];
        int   aa = a_arr[t];
        #pragma unroll
        for (int s = 1; s < 4; s++) {
            float mv = m_arr[s*128 + t];
            if (mv > mm) { mm = mv; aa = a_arr[s*128 + t]; }
        }
        float ss = 0.f;
        #pragma unroll
        for (int s = 0; s < 4; s++)
            ss += s_arr[s*128 + t] * __expf(m_arr[s*128 + t] - mm);
        float pt = 1.0f / ss;
        int cls;
        if (fabsf(pt - 0.6f) < BAND) {
            int slot = atomicAdd(&g_cnt, 1);
            if (slot < MTOT) {
                g_list[slot]   = b*NN + q0 + t;
                g_mval[slot]   = mm;
                g_sumacc[slot] = 0.0;
                g_maxp[slot]   = 0ull;
                cls = 2;
            } else {
                cls = (pt >= 0.6f) ? 1 : 0;
            }
        } else {
            cls = (pt >= 0.6f) ? 1 : 0;
        }
        p_arr[t] = pt; f_arr[t] = cls; a_arr[t] = aa;
    }
    __syncthreads();

    float* Og = Og_ + (size_t)(b*NN + q0)*DD;
    #pragma unroll 4
    for (int i = 0; i < 32; i++) {
        int e4 = t + i*256;
        int row = e4 >> 6, c4 = e4 & 63;
        int cls = f_arr[row];
        if (cls == 2) continue;                // finalize writes this row
        float4 o = ((float4*)bp_s)[c4];
        if (cls == 1) {
            float p = p_arr[row];
            int   a = a_arr[row];
            float4 v = ((const float4*)(VP_ + (size_t)(b*NN + a)*DD))[c4];
            o = make_float4(v.x*p + o.x, v.y*p + o.y, v.z*p + o.z, v.w*p + o.w);
        }
        ((float4*)Og)[(size_t)row*64 + c4] = o;
    }
}

// ---------------- shared-K exact rescue: partial sums per key block ---------
#define KSM_STRIDE 260
#define RS_SMEM (64*KSM_STRIDE*4 + 1024 + 64)

__global__ __launch_bounds__(256) void rescue_sum(const float* __restrict__ Qm,
                                                  const float* __restrict__ y)
{
    extern __shared__ __align__(16) char rsm[];
    float* k_sm = (float*)rsm;                         // 64 x 260
    float* q_sm = (float*)(rsm + 64*KSM_STRIDE*4);     // 256
    double* s_acc = (double*)(rsm + 64*KSM_STRIDE*4 + 1024);
    unsigned long long* s_max = (unsigned long long*)(s_acc + 1);

    const int t = threadIdx.x, lane = t & 31;
    const int kb = blockIdx.x, b = blockIdx.y;
    const int key0 = kb * 64;

    const float* Kb = y + ((size_t)b*NN + key0)*DD;
    for (int i = t; i < 64*64; i += 256) {
        int key = i >> 6, c4 = i & 63;
        *(float4*)&k_sm[key*KSM_STRIDE + c4*4] = ((const float4*)Kb)[i];
    }

    int cnt = g_cnt; if (cnt > MTOT) cnt = MTOT;
    const int key  = t >> 2, part = t & 3;
    const float* krow = k_sm + key*KSM_STRIDE + part*64;

    for (int idx = 0; idx < cnt; idx++) {
        int grow = g_list[idx];
        if ((grow >> 12) != b) continue;               // uniform branch
        if (t == 0) { *s_acc = 0.0; *s_max = 0ull; }
        if (t < 64) ((float4*)q_sm)[t] = ((const float4*)(Qm + (size_t)grow*DD))[t];
        __syncthreads();

        const float* qp = q_sm + part*64;
        float acc = 0.f;
        #pragma unroll 16
        for (int d = 0; d < 64; d++) acc += qp[d] * krow[d];
        acc += __shfl_xor_sync(0xffffffffu, acc, 1);
        acc += __shfl_xor_sync(0xffffffffu, acc, 2);
        float s = acc * SCALE_F;

        float mval = g_mval[idx];
        double exd = 0.0;
        unsigned long long pk = 0ull;
        if ((t & 3) == 0) {
            exd = (double)__expf(s - mval);
            uint32_t u = __float_as_uint(s);
            u = (s >= 0.f) ? (u | 0x80000000u) : ~u;
            pk = ((unsigned long long)u << 32) | (uint32_t)(key0 + key);
        }
        #pragma unroll
        for (int off = 4; off <= 16; off <<= 1) {
            exd += __shfl_xor_sync(0xffffffffu, exd, off);
            unsigned long long op = __shfl_xor_sync(0xffffffffu, pk, off);
            if (op > pk) pk = op;
        }
        if (lane == 0) {
            atomicAdd(s_acc, exd);
            atomicMax(s_max, pk);
        }
        __syncthreads();
        if (t == 0) {
            atomicAdd(&g_sumacc[idx], *s_acc);
            atomicMax(&g_maxp[idx], *s_max);
        }
    }
}

// ---------------- finalize band rows ----------------------------------------
__global__ __launch_bounds__(256) void finalize(const float* __restrict__ VP,
        const float* __restrict__ bp, float* __restrict__ O)
{
    int cnt = g_cnt; if (cnt > MTOT) cnt = MTOT;
    const int t = threadIdx.x;
    for (int idx = blockIdx.x; idx < cnt; idx += gridDim.x) {
        int grow = g_list[idx];
        int b = grow >> 12;
        double S = g_sumacc[idx];
        unsigned long long pk = g_maxp[idx];
        uint32_t u = (uint32_t)(pk >> 32);
        int amax = (int)(pk & 0xffffffffu);
        uint32_t ru = (u & 0x80000000u) ? (u & 0x7fffffffu) : ~u;
        float smax = __uint_as_float(ru);
        double p = exp((double)smax - (double)g_mval[idx]) / S;
        float out;
        if (p >= 0.6) out = (float)p * VP[((size_t)(b*NN) + amax)*DD + t] + bp[t];
        else          out = bp[t];
        O[(size_t)grow*DD + t] = out;
    }
}

// ---------------------------------------------------------------------------
extern "C" void kernel_launch(void* const* d_in, const int* in_sizes, int n_in,
                              void* d_out, int out_size)
{
    const float* x  = (const float*)d_in[0];
    const float* y  = (const float*)d_in[1];
    const float* Wq = (const float*)d_in[2];
    const float* Wk = (const float*)d_in[3];
    const float* Wv = (const float*)d_in[4];
    const float* Wp = (const float*)d_in[5];
    const float* bp = (const float*)d_in[6];
    float* out = (float*)d_out;

    __half *Aaug, *yh, *Wt2;
    float *Qm, *VP;
    void* cntp;
    cudaGetSymbolAddress((void**)&Aaug, g_Aaug);
    cudaGetSymbolAddress((void**)&yh,   g_yh);
    cudaGetSymbolAddress((void**)&Qm,   g_Qm);
    cudaGetSymbolAddress((void**)&VP,   g_VP);
    cudaGetSymbolAddress((void**)&Wt2,  g_Wt2);
    cudaGetSymbolAddress(&cntp,         g_cnt);

    cudaFuncSetAttribute(attn2,
                         cudaFuncAttributeMaxDynamicSharedMemorySize, SMEM_ATTN);
    cudaFuncSetAttribute(rescue_sum,
                         cudaFuncAttributeMaxDynamicSharedMemorySize, RS_SMEM);

    cudaMemsetAsync(cntp, 0, sizeof(int));

    prep_xy<<<4096, 256>>>(x, y, Aaug, yh);
    wgemm_qk<<<dim3(4,4), 256>>>(Wq, Wk, Wt2);
    wgemm_vp<<<dim3(4,4), 256>>>(Wv, Wp, Wt2);

    hgemm2<<<dim3(MTOT/128, 2), 256>>>(Aaug, Wt2, Qm, VP);

    attn2<<<dim3(NN/128, BB), 256, SMEM_ATTN>>>(Qm, yh, VP, bp, out);
    rescue_sum<<<dim3(64, BB), 256, RS_SMEM>>>(Qm, y);
    finalize<<<128, 256>>>(VP, bp, out);
}

// round 13
// speedup vs baseline: 1.1617x; 1.1617x over previous
#include <cuda_runtime.h>
#include <cuda_fp16.h>
#include <math.h>
#include <stdint.h>

#define BB 4
#define NN 4096
#define DD 256
#define MTOT (BB*NN)          // 16384
#define KAUG 768              // 3-term split width (projection GEMM)
#define SCALE_F 0.17677669529663689f
#define BAND 4.0e-3f

// ---------------- static device scratch ------------------------------------
__device__ __half g_Aaug[(size_t)MTOT*KAUG];   // x augmented [h|h|l]
__device__ __half g_yh  [(size_t)MTOT*DD];     // y rounded to fp16 (attn K)
__device__ float  g_Qm  [(size_t)MTOT*DD];     // x . (Wq Wk^T)
__device__ float  g_VP  [(size_t)MTOT*DD];     // x . (Wv Wp)
__device__ __half g_Wt2 [(size_t)2*DD*KAUG];   // [M ; Wvp] split B-style
__device__ float  g_pm[2*MTOT];                // partial max per key-half
__device__ float  g_ps[2*MTOT];                // partial sumexp
__device__ int    g_pa[2*MTOT];                // partial argmax
__device__ int    g_cnt;
__device__ int    g_list[MTOT];
__device__ float  g_mval[MTOT];
__device__ double g_sumacc[MTOT];
__device__ unsigned long long g_maxp[MTOT];

// ---------------- PTX helpers ----------------------------------------------
__device__ __forceinline__ uint32_t smem_u32(const void* p){
    uint32_t a;
    asm("{ .reg .u64 t; cvta.to.shared.u64 t, %1; cvt.u32.u64 %0, t; }" : "=r"(a) : "l"(p));
    return a;
}
#define CP16(dst, src) \
    asm volatile("cp.async.cg.shared.global [%0], [%1], 16;" :: "r"(dst), "l"(src) : "memory")
#define CPC()  asm volatile("cp.async.commit_group;" ::: "memory")
#define CPW0() asm volatile("cp.async.wait_group 0;" ::: "memory")
#define CPW2() asm volatile("cp.async.wait_group 2;" ::: "memory")

__device__ __forceinline__ void ldsm4(uint32_t a, uint32_t& r0, uint32_t& r1,
                                      uint32_t& r2, uint32_t& r3){
    asm volatile("ldmatrix.sync.aligned.m8n8.x4.shared.b16 {%0,%1,%2,%3}, [%4];"
        : "=r"(r0), "=r"(r1), "=r"(r2), "=r"(r3) : "r"(a));
}
__device__ __forceinline__ void mma16816(float* c,
        uint32_t a0, uint32_t a1, uint32_t a2, uint32_t a3,
        uint32_t b0, uint32_t b1){
    asm volatile("mma.sync.aligned.m16n8k16.row.col.f32.f16.f16.f32 "
        "{%0,%1,%2,%3}, {%4,%5,%6,%7}, {%8,%9}, {%0,%1,%2,%3};"
        : "+f"(c[0]), "+f"(c[1]), "+f"(c[2]), "+f"(c[3])
        : "r"(a0), "r"(a1), "r"(a2), "r"(a3), "r"(b0), "r"(b1));
}

// ---------------- fused input prep: x -> Aaug [h|h|l], y -> fp16 ------------
__global__ void prep_xy(const float* __restrict__ x, const float* __restrict__ y,
                        __half* __restrict__ Aaug, __half* __restrict__ yh)
{
    const size_t totalx = (size_t)MTOT * 64;
    const size_t total  = totalx * 2;
    for (size_t i = (size_t)blockIdx.x*blockDim.x + threadIdx.x; i < total;
         i += (size_t)gridDim.x*blockDim.x) {
        if (i < totalx) {
            size_t row = i >> 6; int c4 = (int)(i & 63);
            float4 v = ((const float4*)x)[i];
            __half h0=__float2half_rn(v.x), h1=__float2half_rn(v.y);
            __half h2=__float2half_rn(v.z), h3=__float2half_rn(v.w);
            __half2 H01=__halves2half2(h0,h1), H23=__halves2half2(h2,h3);
            __half2 L01=__halves2half2(__float2half_rn(v.x-__half2float(h0)),
                                       __float2half_rn(v.y-__half2float(h1)));
            __half2 L23=__halves2half2(__float2half_rn(v.z-__half2float(h2)),
                                       __float2half_rn(v.w-__half2float(h3)));
            __half* base = Aaug + row*KAUG + c4*4;
            ((__half2*)base)[0] = H01; ((__half2*)base)[1] = H23;
            ((__half2*)(base+256))[0] = H01; ((__half2*)(base+256))[1] = H23;
            ((__half2*)(base+512))[0] = L01; ((__half2*)(base+512))[1] = L23;
        } else {
            size_t j = i - totalx;
            float4 v = ((const float4*)y)[j];
            ((__half2*)yh)[j*2]   = __halves2half2(__float2half_rn(v.x), __float2half_rn(v.y));
            ((__half2*)yh)[j*2+1] = __halves2half2(__float2half_rn(v.z), __float2half_rn(v.w));
        }
    }
}

// ---------------- weight GEMMs with split epilogue --------------------------
__global__ __launch_bounds__(256) void wgemm_qk(const float* __restrict__ Wq,
                                                const float* __restrict__ Wk,
                                                __half* __restrict__ Wt2)
{
    __shared__ float As[64][17];
    __shared__ float Ws[16][64];
    const int t  = threadIdx.x;
    const int tx = t & 15, ty = t >> 4;
    const int m0 = blockIdx.x * 64, n0 = blockIdx.y * 64;
    const int lr = t >> 2, lc = (t & 3) * 4;
    float acc[4][4] = {};
    for (int kk = 0; kk < 256; kk += 16) {
        float4 av = *(const float4*)(Wq + (size_t)(m0 + lr) * 256 + kk + lc);
        As[lr][lc+0]=av.x; As[lr][lc+1]=av.y; As[lr][lc+2]=av.z; As[lr][lc+3]=av.w;
        #pragma unroll
        for (int i = 0; i < 4; i++)
            Ws[ty][tx*4+i] = Wk[(size_t)(n0 + tx*4 + i) * 256 + kk + ty];
        __syncthreads();
        #pragma unroll
        for (int c = 0; c < 16; c++) {
            float a0=As[ty*4+0][c], a1=As[ty*4+1][c], a2=As[ty*4+2][c], a3=As[ty*4+3][c];
            float4 w = *(const float4*)&Ws[c][tx*4];
            acc[0][0]+=a0*w.x; acc[0][1]+=a0*w.y; acc[0][2]+=a0*w.z; acc[0][3]+=a0*w.w;
            acc[1][0]+=a1*w.x; acc[1][1]+=a1*w.y; acc[1][2]+=a1*w.z; acc[1][3]+=a1*w.w;
            acc[2][0]+=a2*w.x; acc[2][1]+=a2*w.y; acc[2][2]+=a2*w.z; acc[2][3]+=a2*w.w;
            acc[3][0]+=a3*w.x; acc[3][1]+=a3*w.y; acc[3][2]+=a3*w.z; acc[3][3]+=a3*w.w;
        }
        __syncthreads();
    }
    #pragma unroll
    for (int j2 = 0; j2 < 4; j2++) {
        int i = m0 + ty*4 + j2;
        #pragma unroll
        for (int c = 0; c < 4; c++) {
            int n = n0 + tx*4 + c;
            float v = acc[j2][c];
            __half h = __float2half_rn(v);
            __half l = __float2half_rn(v - __half2float(h));
            __half* dst = Wt2 + (size_t)n*KAUG;
            dst[i] = h; dst[256 + i] = l; dst[512 + i] = h;
        }
    }
}

__global__ __launch_bounds__(256) void wgemm_vp(const float* __restrict__ Wv,
                                                const float* __restrict__ Wp,
                                                __half* __restrict__ Wt2)
{
    __shared__ float As[64][17];
    __shared__ float Ws[16][64];
    const int t  = threadIdx.x;
    const int tx = t & 15, ty = t >> 4;
    const int m0 = blockIdx.x * 64, n0 = blockIdx.y * 64;
    const int lr = t >> 2, lc = (t & 3) * 4;
    float acc[4][4] = {};
    for (int kk = 0; kk < 256; kk += 16) {
        float4 av = *(const float4*)(Wv + (size_t)(m0 + lr) * 256 + kk + lc);
        As[lr][lc+0]=av.x; As[lr][lc+1]=av.y; As[lr][lc+2]=av.z; As[lr][lc+3]=av.w;
        float4 wv = *(const float4*)(Wp + (size_t)(kk + ty) * 256 + n0 + tx * 4);
        *(float4*)&Ws[ty][tx*4] = wv;
        __syncthreads();
        #pragma unroll
        for (int c = 0; c < 16; c++) {
            float a0=As[ty*4+0][c], a1=As[ty*4+1][c], a2=As[ty*4+2][c], a3=As[ty*4+3][c];
            float4 w = *(const float4*)&Ws[c][tx*4];
            acc[0][0]+=a0*w.x; acc[0][1]+=a0*w.y; acc[0][2]+=a0*w.z; acc[0][3]+=a0*w.w;
            acc[1][0]+=a1*w.x; acc[1][1]+=a1*w.y; acc[1][2]+=a1*w.z; acc[1][3]+=a1*w.w;
            acc[2][0]+=a2*w.x; acc[2][1]+=a2*w.y; acc[2][2]+=a2*w.z; acc[2][3]+=a2*w.w;
            acc[3][0]+=a3*w.x; acc[3][1]+=a3*w.y; acc[3][2]+=a3*w.z; acc[3][3]+=a3*w.w;
        }
        __syncthreads();
    }
    #pragma unroll
    for (int j2 = 0; j2 < 4; j2++) {
        int i = m0 + ty*4 + j2;
        #pragma unroll
        for (int c = 0; c < 4; c++) {
            int n = n0 + tx*4 + c;
            float v = acc[j2][c];
            __half h = __float2half_rn(v);
            __half l = __float2half_rn(v - __half2float(h));
            __half* dst = Wt2 + (size_t)(256 + n)*KAUG;
            dst[i] = h; dst[256 + i] = l; dst[512 + i] = h;
        }
    }
}

// ---------------- fused HMMA GEMM (R11 version): [Qm | VP] = Aaug . Wt2^T ---
__global__ __launch_bounds__(256) void hgemm2(const __half* __restrict__ A,
                                              const __half* __restrict__ Bw,
                                              float* __restrict__ Qm,
                                              float* __restrict__ VP)
{
    __shared__ __align__(16) char sm[4*10240];
    const uint32_t sb = smem_u32(sm);
    const int t = threadIdx.x, lane = t & 31, wid = t >> 5;
    const int wm = wid >> 1, wn = wid & 1;
    const int m0 = blockIdx.x * 128, n0 = blockIdx.y * 128;
    float* C   = (blockIdx.y < 2) ? Qm : VP;
    const int coff = (blockIdx.y < 2) ? 0 : 256;

    float c[2][8][4] = {};
    {
        #pragma unroll
        for (int i = 0; i < 2; i++) {
            int sidx = t*2 + i; int row = sidx >> 2, seg = sidx & 3;
            CP16(sb + row*80 + seg*16,           A  + (size_t)(m0+row)*KAUG + seg*8);
            CP16(sb + 20480 + row*80 + seg*16,   Bw + (size_t)(n0+row)*KAUG + seg*8);
        }
        CPC();
    }
    const uint32_t aRowOff = (uint32_t)(wm*32 + (lane&15))*80 + ((lane>>4)&1)*16;
    const uint32_t bRowOff = (uint32_t)(wn*64 + (lane&7) + ((lane>>3)&1)*8)*80
                           + ((lane>>4)&1)*16;

    for (int ch = 0; ch < 24; ch++) {
        int buf = ch & 1;
        CPW0();
        __syncthreads();
        if (ch + 1 < 24) {
            int nb = buf ^ 1;
            #pragma unroll
            for (int i = 0; i < 2; i++) {
                int sidx = t*2 + i; int row = sidx >> 2, seg = sidx & 3;
                CP16(sb + nb*10240 + row*80 + seg*16,
                     A  + (size_t)(m0+row)*KAUG + (ch+1)*32 + seg*8);
                CP16(sb + 20480 + nb*10240 + row*80 + seg*16,
                     Bw + (size_t)(n0+row)*KAUG + (ch+1)*32 + seg*8);
            }
            CPC();
        }
        uint32_t aBase = sb + buf*10240 + aRowOff;
        uint32_t bBase = sb + 20480 + buf*10240 + bRowOff;
        #pragma unroll
        for (int ks = 0; ks < 2; ks++) {
            uint32_t a0,a1,a2,a3,a4,a5,a6,a7;
            ldsm4(aBase + ks*32,            a0,a1,a2,a3);
            ldsm4(aBase + 16*80 + ks*32,    a4,a5,a6,a7);
            #pragma unroll
            for (int p = 0; p < 4; p++) {
                uint32_t b0,b1,b2,b3;
                ldsm4(bBase + p*1280 + ks*32, b0,b1,b2,b3);
                mma16816(c[0][2*p+0], a0,a1,a2,a3, b0,b2);
                mma16816(c[0][2*p+1], a0,a1,a2,a3, b1,b3);
                mma16816(c[1][2*p+0], a4,a5,a6,a7, b0,b2);
                mma16816(c[1][2*p+1], a4,a5,a6,a7, b1,b3);
            }
        }
    }
    #pragma unroll
    for (int mi = 0; mi < 2; mi++)
        #pragma unroll
        for (int ni = 0; ni < 8; ni++) {
            int row = m0 + wm*32 + mi*16 + (lane>>2);
            int col = n0 - coff + wn*64 + ni*8 + 2*(lane&3);
            *(float2*)(C + (size_t)row*DD + col) =
                make_float2(c[mi][ni][0], c[mi][ni][1]);
            *(float2*)(C + (size_t)(row+8)*DD + col) =
                make_float2(c[mi][ni][2], c[mi][ni][3]);
        }
}

// ---------------- 1-term attention, key-split x2, 2 CTAs/SM -----------------
// grid (32, BB, 2). Each CTA: 128 q-rows x 2048 keys, 32-dim chunk stages.
#define AQ_STRIDE  528                         // 256 half + 16B pad
#define AQS        (128*AQ_STRIDE)             // 67584
#define KB_OFF     AQS
#define KST        (128*80)                    // 32-dim chunk, 128 keys
#define MRG        (KB_OFF + 4*KST)            // 108544
#define SMEM_ATTN  (MRG + 3072)                // 111616 (2 CTAs/SM)

__global__ __launch_bounds__(256, 2) void attn2(const float* __restrict__ Qm_,
        const __half* __restrict__ yh_)
{
    extern __shared__ __align__(128) char smem[];
    const uint32_t sb = smem_u32(smem);
    const int t = threadIdx.x, lane = t & 31, wid = t >> 5;
    const int wm = wid >> 1, wn = wid & 1;
    const int b = blockIdx.y, q0 = blockIdx.x * 128;
    const int part = blockIdx.z;                 // key half

    const __half* Kb = yh_ + ((size_t)b*NN + part*2048)*DD;

    // prologue: 3 chunks (key-tile 0, dim-chunks 0..2)
    #pragma unroll
    for (int st = 0; st < 3; st++) {
        #pragma unroll
        for (int i = 0; i < 2; i++) {
            int sidx = t*2 + i; int row = sidx >> 2, seg = sidx & 3;
            CP16(sb + KB_OFF + st*KST + row*80 + seg*16,
                 Kb + (size_t)row*DD + st*32 + seg*8);
        }
        CPC();
    }

    // build Qh tile (pre-scaled, rounded to fp16)
    const float* Qg = Qm_ + (size_t)(b*NN + q0)*DD;
    #pragma unroll 4
    for (int i = 0; i < 32; i++) {
        int e4 = t + i*256;
        int row = e4 >> 6, c4 = e4 & 63;
        float4 v = ((const float4*)Qg)[(size_t)row*64 + c4];
        __half2 H01 = __halves2half2(__float2half_rn(v.x*SCALE_F),
                                     __float2half_rn(v.y*SCALE_F));
        __half2 H23 = __halves2half2(__float2half_rn(v.z*SCALE_F),
                                     __float2half_rn(v.w*SCALE_F));
        char* base = smem + (size_t)row*AQ_STRIDE + (size_t)c4*8;
        *(__half2*)(base)   = H01;
        *(__half2*)(base+4) = H23;
    }

    float c[2][8][4] = {};
    float rm[4], rs[4]; int ra[4];
    #pragma unroll
    for (int j = 0; j < 4; j++) { rm[j] = -3.0e38f; rs[j] = 0.f; ra[j] = 0; }

    const uint32_t aRowOff = (uint32_t)(wm*32 + (lane&15))*AQ_STRIDE + ((lane>>4)&1)*16;
    const uint32_t bRowOff = (uint32_t)(wn*64 + (lane&7) + ((lane>>3)&1)*8)*80
                           + ((lane>>4)&1)*16;

    // 16 key-tiles x 8 dim-chunks = 128 iterations
    for (int idx = 0; idx < 128; idx++) {
        CPW2();                        // chunk idx resident (<=2 pending)
        __syncthreads();
        if (idx + 3 < 128) {
            int nx = idx + 3, nkt = nx >> 3, nch = nx & 7, nb = nx & 3;
            #pragma unroll
            for (int i = 0; i < 2; i++) {
                int sidx = t*2 + i; int row = sidx >> 2, seg = sidx & 3;
                CP16(sb + KB_OFF + nb*KST + row*80 + seg*16,
                     Kb + (size_t)(nkt*128+row)*DD + nch*32 + seg*8);
            }
            CPC();
        }
        uint32_t aBase = sb + aRowOff + (uint32_t)(idx & 7)*64;
        uint32_t bBase = sb + KB_OFF + (idx & 3)*KST + bRowOff;
        #pragma unroll
        for (int ks = 0; ks < 2; ks++) {
            uint32_t a0,a1,a2,a3,a4,a5,a6,a7;
            ldsm4(aBase + ks*32,                  a0,a1,a2,a3);
            ldsm4(aBase + 16*AQ_STRIDE + ks*32,   a4,a5,a6,a7);
            #pragma unroll
            for (int p = 0; p < 4; p++) {
                uint32_t b0,b1,b2,b3;
                ldsm4(bBase + p*1280 + ks*32, b0,b1,b2,b3);
                mma16816(c[0][2*p+0], a0,a1,a2,a3, b0,b2);
                mma16816(c[0][2*p+1], a0,a1,a2,a3, b1,b3);
                mma16816(c[1][2*p+0], a4,a5,a6,a7, b0,b2);
                mma16816(c[1][2*p+1], a4,a5,a6,a7, b1,b3);
            }
        }

        if ((idx & 7) == 7) {
            int kt = idx >> 3;
            #pragma unroll
            for (int j = 0; j < 4; j++) {
                int mi = j >> 1, hr = (j & 1) * 2;
                float tm = -3.0e38f; int ta = 0;
                #pragma unroll
                for (int ni = 0; ni < 8; ni++) {
                    float v0 = c[mi][ni][hr], v1 = c[mi][ni][hr+1];
                    int col = ni*8 + 2*(lane&3);
                    if (v0 > tm) { tm = v0; ta = col; }
                    if (v1 > tm) { tm = v1; ta = col+1; }
                }
                #pragma unroll
                for (int off = 1; off <= 2; off <<= 1) {
                    float om = __shfl_xor_sync(0xffffffffu, tm, off);
                    int   oa = __shfl_xor_sync(0xffffffffu, ta, off);
                    if (om > tm || (om == tm && oa < ta)) { tm = om; ta = oa; }
                }
                float ts = 0.f;
                #pragma unroll
                for (int ni = 0; ni < 8; ni++) {
                    ts += __expf(c[mi][ni][hr]   - tm);
                    ts += __expf(c[mi][ni][hr+1] - tm);
                }
                #pragma unroll
                for (int off = 1; off <= 2; off <<= 1)
                    ts += __shfl_xor_sync(0xffffffffu, ts, off);
                if (tm > rm[j]) {
                    rs[j] = rs[j]*__expf(rm[j]-tm) + ts;
                    rm[j] = tm;
                    ra[j] = part*2048 + kt*128 + wn*64 + ta;
                } else {
                    rs[j] += ts*__expf(tm - rm[j]);
                }
            }
            #pragma unroll
            for (int mi = 0; mi < 2; mi++)
                #pragma unroll
                for (int ni = 0; ni < 8; ni++)
                    #pragma unroll
                    for (int r = 0; r < 4; r++) c[mi][ni][r] = 0.f;
        }
    }

    // ---- merge 2 n-halves, write per-half partial stats to global ----
    float* m_arr = (float*)(smem + MRG);           // [256]
    float* s_arr = (float*)(smem + MRG + 1024);    // [256]
    int*   a_arr = (int*)  (smem + MRG + 2048);    // [256]
    if ((lane & 3) == 0) {
        #pragma unroll
        for (int j = 0; j < 4; j++) {
            int row = wm*32 + (j>>1)*16 + (j&1)*8 + (lane>>2);
            m_arr[wn*128 + row] = rm[j];
            s_arr[wn*128 + row] = rs[j];
            a_arr[wn*128 + row] = ra[j];
        }
    }
    __syncthreads();
    if (t < 128) {
        float m0v = m_arr[t], m1v = m_arr[128+t];
        float s0  = s_arr[t], s1  = s_arr[128+t];
        float mm  = fmaxf(m0v, m1v);
        float ss  = s0*__expf(m0v-mm) + s1*__expf(m1v-mm);
        int   aa  = (m0v >= m1v) ? a_arr[t] : a_arr[128+t];
        size_t gi = (size_t)part*MTOT + b*NN + q0 + t;
        g_pm[gi] = mm; g_ps[gi] = ss; g_pa[gi] = aa;
    }
}

// ---------------- merge key-halves, classify, write output ------------------
__global__ __launch_bounds__(256) void merge_cls(const float* __restrict__ VP_,
        const float* __restrict__ bp, float* __restrict__ Og_)
{
    __shared__ float p_s[128];
    __shared__ int   f_s[128];
    __shared__ int   a_s[128];
    __shared__ float bp_s[256];
    const int t = threadIdx.x;
    const int base = blockIdx.x * 128;            // global row base

    if (t < 64) ((float4*)bp_s)[t] = ((const float4*)bp)[t];
    if (t < 128) {
        int row = base + t;
        float m0v = g_pm[row], m1v = g_pm[MTOT + row];
        float s0  = g_ps[row], s1  = g_ps[MTOT + row];
        float mm  = fmaxf(m0v, m1v);
        float ss  = s0*__expf(m0v-mm) + s1*__expf(m1v-mm);
        int   aa  = (m0v >= m1v) ? g_pa[row] : g_pa[MTOT + row];
        float pt  = 1.0f / ss;
        int cls;
        if (fabsf(pt - 0.6f) < BAND) {
            int slot = atomicAdd(&g_cnt, 1);
            if (slot < MTOT) {
                g_list[slot]   = row;
                g_mval[slot]   = mm;
                g_sumacc[slot] = 0.0;
                g_maxp[slot]   = 0ull;
                cls = 2;
            } else {
                cls = (pt >= 0.6f) ? 1 : 0;
            }
        } else {
            cls = (pt >= 0.6f) ? 1 : 0;
        }
        p_s[t] = pt; f_s[t] = cls; a_s[t] = aa;
    }
    __syncthreads();

    #pragma unroll 4
    for (int i = 0; i < 32; i++) {
        int e4 = t + i*256;
        int row = e4 >> 6, c4 = e4 & 63;
        int cls = f_s[row];
        if (cls == 2) continue;                // finalize writes this row
        int grow = base + row;
        float4 o = ((float4*)bp_s)[c4];
        if (cls == 1) {
            float p = p_s[row];
            int   a = a_s[row];
            int   b = grow >> 12;
            float4 v = ((const float4*)(VP_ + (size_t)(b*NN + a)*DD))[c4];
            o = make_float4(v.x*p + o.x, v.y*p + o.y, v.z*p + o.z, v.w*p + o.w);
        }
        ((float4*)(Og_ + (size_t)grow*DD))[c4] = o;
    }
}

// ---------------- shared-K exact rescue: partial sums per key block ---------
#define KSM_STRIDE 260
#define RS_SMEM (64*KSM_STRIDE*4 + 1024 + 64)

__global__ __launch_bounds__(256) void rescue_sum(const float* __restrict__ Qm,
                                                  const float* __restrict__ y)
{
    extern __shared__ __align__(16) char rsm[];
    float* k_sm = (float*)rsm;                         // 64 x 260
    float* q_sm = (float*)(rsm + 64*KSM_STRIDE*4);     // 256
    double* s_acc = (double*)(rsm + 64*KSM_STRIDE*4 + 1024);
    unsigned long long* s_max = (unsigned long long*)(s_acc + 1);

    const int t = threadIdx.x, lane = t & 31;
    const int kb = blockIdx.x, b = blockIdx.y;
    const int key0 = kb * 64;

    const float* Kb = y + ((size_t)b*NN + key0)*DD;
    for (int i = t; i < 64*64; i += 256) {
        int key = i >> 6, c4 = i & 63;
        *(float4*)&k_sm[key*KSM_STRIDE + c4*4] = ((const float4*)Kb)[i];
    }

    int cnt = g_cnt; if (cnt > MTOT) cnt = MTOT;
    const int key  = t >> 2, part = t & 3;
    const float* krow = k_sm + key*KSM_STRIDE + part*64;

    for (int idx = 0; idx < cnt; idx++) {
        int grow = g_list[idx];
        if ((grow >> 12) != b) continue;               // uniform branch
        if (t == 0) { *s_acc = 0.0; *s_max = 0ull; }
        if (t < 64) ((float4*)q_sm)[t] = ((const float4*)(Qm + (size_t)grow*DD))[t];
        __syncthreads();

        const float* qp = q_sm + part*64;
        float acc = 0.f;
        #pragma unroll 16
        for (int d = 0; d < 64; d++) acc += qp[d] * krow[d];
        acc += __shfl_xor_sync(0xffffffffu, acc, 1);
        acc += __shfl_xor_sync(0xffffffffu, acc, 2);
        float s = acc * SCALE_F;

        float mval = g_mval[idx];
        double exd = 0.0;
        unsigned long long pk = 0ull;
        if ((t & 3) == 0) {
            exd = (double)__expf(s - mval);
            uint32_t u = __float_as_uint(s);
            u = (s >= 0.f) ? (u | 0x80000000u) : ~u;
            pk = ((unsigned long long)u << 32) | (uint32_t)(key0 + key);
        }
        #pragma unroll
        for (int off = 4; off <= 16; off <<= 1) {
            exd += __shfl_xor_sync(0xffffffffu, exd, off);
            unsigned long long op = __shfl_xor_sync(0xffffffffu, pk, off);
            if (op > pk) pk = op;
        }
        if (lane == 0) {
            atomicAdd(s_acc, exd);
            atomicMax(s_max, pk);
        }
        __syncthreads();
        if (t == 0) {
            atomicAdd(&g_sumacc[idx], *s_acc);
            atomicMax(&g_maxp[idx], *s_max);
        }
    }
}

// ---------------- finalize band rows ----------------------------------------
__global__ __launch_bounds__(256) void finalize(const float* __restrict__ VP,
        const float* __restrict__ bp, float* __restrict__ O)
{
    int cnt = g_cnt; if (cnt > MTOT) cnt = MTOT;
    const int t = threadIdx.x;
    for (int idx = blockIdx.x; idx < cnt; idx += gridDim.x) {
        int grow = g_list[idx];
        int b = grow >> 12;
        double S = g_sumacc[idx];
        unsigned long long pk = g_maxp[idx];
        uint32_t u = (uint32_t)(pk >> 32);
        int amax = (int)(pk & 0xffffffffu);
        uint32_t ru = (u & 0x80000000u) ? (u & 0x7fffffffu) : ~u;
        float smax = __uint_as_float(ru);
        double p = exp((double)smax - (double)g_mval[idx]) / S;
        float out;
        if (p >= 0.6) out = (float)p * VP[((size_t)(b*NN) + amax)*DD + t] + bp[t];
        else          out = bp[t];
        O[(size_t)grow*DD + t] = out;
    }
}

// ---------------------------------------------------------------------------
extern "C" void kernel_launch(void* const* d_in, const int* in_sizes, int n_in,
                              void* d_out, int out_size)
{
    const float* x  = (const float*)d_in[0];
    const float* y  = (const float*)d_in[1];
    const float* Wq = (const float*)d_in[2];
    const float* Wk = (const float*)d_in[3];
    const float* Wv = (const float*)d_in[4];
    const float* Wp = (const float*)d_in[5];
    const float* bp = (const float*)d_in[6];
    float* out = (float*)d_out;

    __half *Aaug, *yh, *Wt2;
    float *Qm, *VP;
    void* cntp;
    cudaGetSymbolAddress((void**)&Aaug, g_Aaug);
    cudaGetSymbolAddress((void**)&yh,   g_yh);
    cudaGetSymbolAddress((void**)&Qm,   g_Qm);
    cudaGetSymbolAddress((void**)&VP,   g_VP);
    cudaGetSymbolAddress((void**)&Wt2,  g_Wt2);
    cudaGetSymbolAddress(&cntp,         g_cnt);

    cudaFuncSetAttribute(attn2,
                         cudaFuncAttributeMaxDynamicSharedMemorySize, SMEM_ATTN);
    cudaFuncSetAttribute(rescue_sum,
                         cudaFuncAttributeMaxDynamicSharedMemorySize, RS_SMEM);

    cudaMemsetAsync(cntp, 0, sizeof(int));

    prep_xy<<<4096, 256>>>(x, y, Aaug, yh);
    wgemm_qk<<<dim3(4,4), 256>>>(Wq, Wk, Wt2);
    wgemm_vp<<<dim3(4,4), 256>>>(Wv, Wp, Wt2);

    hgemm2<<<dim3(MTOT/128, 4), 256>>>(Aaug, Wt2, Qm, VP);

    attn2<<<dim3(NN/128, BB, 2), 256, SMEM_ATTN>>>(Qm, yh);
    merge_cls<<<MTOT/128, 256>>>(VP, bp, out);
    rescue_sum<<<dim3(64, BB), 256, RS_SMEM>>>(Qm, y);
    finalize<<<128, 256>>>(VP, bp, out);
}

// round 14
// speedup vs baseline: 1.1984x; 1.0316x over previous
#include <cuda_runtime.h>
#include <cuda_fp16.h>
#include <math.h>
#include <stdint.h>

#define BB 4
#define NN 4096
#define DD 256
#define MTOT (BB*NN)          // 16384
#define KAUG 768              // 3-term split width (projection GEMM)
#define SCALE_F 0.17677669529663689f
#define LOG2E   1.4426950408889634f
#define S2F     (SCALE_F*LOG2E)               // base-2 score scale
#define BAND 4.0e-3f

// ---------------- static device scratch ------------------------------------
__device__ __half g_Aaug[(size_t)MTOT*KAUG];   // x augmented [h|h|l]
__device__ __half g_yh  [(size_t)MTOT*DD];     // y rounded to fp16 (attn K)
__device__ float  g_Qm  [(size_t)MTOT*DD];     // x . (Wq Wk^T)  (exact, for rescue)
__device__ __half g_Qh  [(size_t)MTOT*DD];     // fp16(Qm * SCALE * log2e)
__device__ float  g_VP  [(size_t)MTOT*DD];     // x . (Wv Wp)
__device__ __half g_Wt2 [(size_t)2*DD*KAUG];   // [M ; Wvp] split B-style
__device__ float  g_pm[2*MTOT];                // partial max (base-2) per key-half
__device__ float  g_ps[2*MTOT];                // partial sumexp2
__device__ int    g_pa[2*MTOT];                // partial argmax
__device__ int    g_cnt;
__device__ int    g_list[MTOT];
__device__ float  g_mval[MTOT];
__device__ double g_sumacc[MTOT];
__device__ unsigned long long g_maxp[MTOT];

// ---------------- PTX helpers ----------------------------------------------
__device__ __forceinline__ uint32_t smem_u32(const void* p){
    uint32_t a;
    asm("{ .reg .u64 t; cvta.to.shared.u64 t, %1; cvt.u32.u64 %0, t; }" : "=r"(a) : "l"(p));
    return a;
}
#define CP16(dst, src) \
    asm volatile("cp.async.cg.shared.global [%0], [%1], 16;" :: "r"(dst), "l"(src) : "memory")
#define CPC()  asm volatile("cp.async.commit_group;" ::: "memory")
#define CPW0() asm volatile("cp.async.wait_group 0;" ::: "memory")
#define CPW2() asm volatile("cp.async.wait_group 2;" ::: "memory")

__device__ __forceinline__ void ldsm4(uint32_t a, uint32_t& r0, uint32_t& r1,
                                      uint32_t& r2, uint32_t& r3){
    asm volatile("ldmatrix.sync.aligned.m8n8.x4.shared.b16 {%0,%1,%2,%3}, [%4];"
        : "=r"(r0), "=r"(r1), "=r"(r2), "=r"(r3) : "r"(a));
}
__device__ __forceinline__ void mma16816(float* c,
        uint32_t a0, uint32_t a1, uint32_t a2, uint32_t a3,
        uint32_t b0, uint32_t b1){
    asm volatile("mma.sync.aligned.m16n8k16.row.col.f32.f16.f16.f32 "
        "{%0,%1,%2,%3}, {%4,%5,%6,%7}, {%8,%9}, {%0,%1,%2,%3};"
        : "+f"(c[0]), "+f"(c[1]), "+f"(c[2]), "+f"(c[3])
        : "r"(a0), "r"(a1), "r"(a2), "r"(a3), "r"(b0), "r"(b1));
}

// ---------------- fused input prep: x -> Aaug [h|h|l], y -> fp16 ------------
__global__ void prep_xy(const float* __restrict__ x, const float* __restrict__ y,
                        __half* __restrict__ Aaug, __half* __restrict__ yh)
{
    const size_t totalx = (size_t)MTOT * 64;
    const size_t total  = totalx * 2;
    for (size_t i = (size_t)blockIdx.x*blockDim.x + threadIdx.x; i < total;
         i += (size_t)gridDim.x*blockDim.x) {
        if (i < totalx) {
            size_t row = i >> 6; int c4 = (int)(i & 63);
            float4 v = ((const float4*)x)[i];
            __half h0=__float2half_rn(v.x), h1=__float2half_rn(v.y);
            __half h2=__float2half_rn(v.z), h3=__float2half_rn(v.w);
            __half2 H01=__halves2half2(h0,h1), H23=__halves2half2(h2,h3);
            __half2 L01=__halves2half2(__float2half_rn(v.x-__half2float(h0)),
                                       __float2half_rn(v.y-__half2float(h1)));
            __half2 L23=__halves2half2(__float2half_rn(v.z-__half2float(h2)),
                                       __float2half_rn(v.w-__half2float(h3)));
            __half* base = Aaug + row*KAUG + c4*4;
            ((__half2*)base)[0] = H01; ((__half2*)base)[1] = H23;
            ((__half2*)(base+256))[0] = H01; ((__half2*)(base+256))[1] = H23;
            ((__half2*)(base+512))[0] = L01; ((__half2*)(base+512))[1] = L23;
        } else {
            size_t j = i - totalx;
            float4 v = ((const float4*)y)[j];
            ((__half2*)yh)[j*2]   = __halves2half2(__float2half_rn(v.x), __float2half_rn(v.y));
            ((__half2*)yh)[j*2+1] = __halves2half2(__float2half_rn(v.z), __float2half_rn(v.w));
        }
    }
}

// ---------------- weight GEMMs with split epilogue --------------------------
__global__ __launch_bounds__(256) void wgemm_qk(const float* __restrict__ Wq,
                                                const float* __restrict__ Wk,
                                                __half* __restrict__ Wt2)
{
    __shared__ float As[64][17];
    __shared__ float Ws[16][64];
    const int t  = threadIdx.x;
    const int tx = t & 15, ty = t >> 4;
    const int m0 = blockIdx.x * 64, n0 = blockIdx.y * 64;
    const int lr = t >> 2, lc = (t & 3) * 4;
    float acc[4][4] = {};
    for (int kk = 0; kk < 256; kk += 16) {
        float4 av = *(const float4*)(Wq + (size_t)(m0 + lr) * 256 + kk + lc);
        As[lr][lc+0]=av.x; As[lr][lc+1]=av.y; As[lr][lc+2]=av.z; As[lr][lc+3]=av.w;
        #pragma unroll
        for (int i = 0; i < 4; i++)
            Ws[ty][tx*4+i] = Wk[(size_t)(n0 + tx*4 + i) * 256 + kk + ty];
        __syncthreads();
        #pragma unroll
        for (int c = 0; c < 16; c++) {
            float a0=As[ty*4+0][c], a1=As[ty*4+1][c], a2=As[ty*4+2][c], a3=As[ty*4+3][c];
            float4 w = *(const float4*)&Ws[c][tx*4];
            acc[0][0]+=a0*w.x; acc[0][1]+=a0*w.y; acc[0][2]+=a0*w.z; acc[0][3]+=a0*w.w;
            acc[1][0]+=a1*w.x; acc[1][1]+=a1*w.y; acc[1][2]+=a1*w.z; acc[1][3]+=a1*w.w;
            acc[2][0]+=a2*w.x; acc[2][1]+=a2*w.y; acc[2][2]+=a2*w.z; acc[2][3]+=a2*w.w;
            acc[3][0]+=a3*w.x; acc[3][1]+=a3*w.y; acc[3][2]+=a3*w.z; acc[3][3]+=a3*w.w;
        }
        __syncthreads();
    }
    #pragma unroll
    for (int j2 = 0; j2 < 4; j2++) {
        int i = m0 + ty*4 + j2;
        #pragma unroll
        for (int c = 0; c < 4; c++) {
            int n = n0 + tx*4 + c;
            float v = acc[j2][c];
            __half h = __float2half_rn(v);
            __half l = __float2half_rn(v - __half2float(h));
            __half* dst = Wt2 + (size_t)n*KAUG;
            dst[i] = h; dst[256 + i] = l; dst[512 + i] = h;
        }
    }
}

__global__ __launch_bounds__(256) void wgemm_vp(const float* __restrict__ Wv,
                                                const float* __restrict__ Wp,
                                                __half* __restrict__ Wt2)
{
    __shared__ float As[64][17];
    __shared__ float Ws[16][64];
    const int t  = threadIdx.x;
    const int tx = t & 15, ty = t >> 4;
    const int m0 = blockIdx.x * 64, n0 = blockIdx.y * 64;
    const int lr = t >> 2, lc = (t & 3) * 4;
    float acc[4][4] = {};
    for (int kk = 0; kk < 256; kk += 16) {
        float4 av = *(const float4*)(Wv + (size_t)(m0 + lr) * 256 + kk + lc);
        As[lr][lc+0]=av.x; As[lr][lc+1]=av.y; As[lr][lc+2]=av.z; As[lr][lc+3]=av.w;
        float4 wv = *(const float4*)(Wp + (size_t)(kk + ty) * 256 + n0 + tx * 4);
        *(float4*)&Ws[ty][tx*4] = wv;
        __syncthreads();
        #pragma unroll
        for (int c = 0; c < 16; c++) {
            float a0=As[ty*4+0][c], a1=As[ty*4+1][c], a2=As[ty*4+2][c], a3=As[ty*4+3][c];
            float4 w = *(const float4*)&Ws[c][tx*4];
            acc[0][0]+=a0*w.x; acc[0][1]+=a0*w.y; acc[0][2]+=a0*w.z; acc[0][3]+=a0*w.w;
            acc[1][0]+=a1*w.x; acc[1][1]+=a1*w.y; acc[1][2]+=a1*w.z; acc[1][3]+=a1*w.w;
            acc[2][0]+=a2*w.x; acc[2][1]+=a2*w.y; acc[2][2]+=a2*w.z; acc[2][3]+=a2*w.w;
            acc[3][0]+=a3*w.x; acc[3][1]+=a3*w.y; acc[3][2]+=a3*w.z; acc[3][3]+=a3*w.w;
        }
        __syncthreads();
    }
    #pragma unroll
    for (int j2 = 0; j2 < 4; j2++) {
        int i = m0 + ty*4 + j2;
        #pragma unroll
        for (int c = 0; c < 4; c++) {
            int n = n0 + tx*4 + c;
            float v = acc[j2][c];
            __half h = __float2half_rn(v);
            __half l = __float2half_rn(v - __half2float(h));
            __half* dst = Wt2 + (size_t)(256 + n)*KAUG;
            dst[i] = h; dst[256 + i] = l; dst[512 + i] = h;
        }
    }
}

// ---------------- fused HMMA GEMM: [Qm | VP] = Aaug . Wt2^T -----------------
// Qm (blockIdx.y<2): full 24 chunks (3-term). VP (y>=2): 16 chunks (2-term).
// Qm epilogue also writes pre-scaled fp16 Qh.
__global__ __launch_bounds__(256) void hgemm2(const __half* __restrict__ A,
                                              const __half* __restrict__ Bw,
                                              float* __restrict__ Qm,
                                              __half* __restrict__ Qh,
                                              float* __restrict__ VP)
{
    __shared__ __align__(16) char sm[4*10240];
    const uint32_t sb = smem_u32(sm);
    const int t = threadIdx.x, lane = t & 31, wid = t >> 5;
    const int wm = wid >> 1, wn = wid & 1;
    const int m0 = blockIdx.x * 128, n0 = blockIdx.y * 128;
    const bool isQ = (blockIdx.y < 2);
    float* C   = isQ ? Qm : VP;
    const int coff = isQ ? 0 : 256;
    const int NCH = isQ ? 24 : 16;

    float c[2][8][4] = {};
    {
        #pragma unroll
        for (int i = 0; i < 2; i++) {
            int sidx = t*2 + i; int row = sidx >> 2, seg = sidx & 3;
            CP16(sb + row*80 + seg*16,           A  + (size_t)(m0+row)*KAUG + seg*8);
            CP16(sb + 20480 + row*80 + seg*16,   Bw + (size_t)(n0+row)*KAUG + seg*8);
        }
        CPC();
    }
    const uint32_t aRowOff = (uint32_t)(wm*32 + (lane&15))*80 + ((lane>>4)&1)*16;
    const uint32_t bRowOff = (uint32_t)(wn*64 + (lane&7) + ((lane>>3)&1)*8)*80
                           + ((lane>>4)&1)*16;

    for (int ch = 0; ch < NCH; ch++) {
        int buf = ch & 1;
        CPW0();
        __syncthreads();
        if (ch + 1 < NCH) {
            int nb = buf ^ 1;
            #pragma unroll
            for (int i = 0; i < 2; i++) {
                int sidx = t*2 + i; int row = sidx >> 2, seg = sidx & 3;
                CP16(sb + nb*10240 + row*80 + seg*16,
                     A  + (size_t)(m0+row)*KAUG + (ch+1)*32 + seg*8);
                CP16(sb + 20480 + nb*10240 + row*80 + seg*16,
                     Bw + (size_t)(n0+row)*KAUG + (ch+1)*32 + seg*8);
            }
            CPC();
        }
        uint32_t aBase = sb + buf*10240 + aRowOff;
        uint32_t bBase = sb + 20480 + buf*10240 + bRowOff;
        #pragma unroll
        for (int ks = 0; ks < 2; ks++) {
            uint32_t a0,a1,a2,a3,a4,a5,a6,a7;
            ldsm4(aBase + ks*32,            a0,a1,a2,a3);
            ldsm4(aBase + 16*80 + ks*32,    a4,a5,a6,a7);
            #pragma unroll
            for (int p = 0; p < 4; p++) {
                uint32_t b0,b1,b2,b3;
                ldsm4(bBase + p*1280 + ks*32, b0,b1,b2,b3);
                mma16816(c[0][2*p+0], a0,a1,a2,a3, b0,b2);
                mma16816(c[0][2*p+1], a0,a1,a2,a3, b1,b3);
                mma16816(c[1][2*p+0], a4,a5,a6,a7, b0,b2);
                mma16816(c[1][2*p+1], a4,a5,a6,a7, b1,b3);
            }
        }
    }
    #pragma unroll
    for (int mi = 0; mi < 2; mi++)
        #pragma unroll
        for (int ni = 0; ni < 8; ni++) {
            int row = m0 + wm*32 + mi*16 + (lane>>2);
            int col = n0 - coff + wn*64 + ni*8 + 2*(lane&3);
            float v00 = c[mi][ni][0], v01 = c[mi][ni][1];
            float v10 = c[mi][ni][2], v11 = c[mi][ni][3];
            *(float2*)(C + (size_t)row*DD + col)     = make_float2(v00, v01);
            *(float2*)(C + (size_t)(row+8)*DD + col) = make_float2(v10, v11);
            if (isQ) {
                *(__half2*)(Qh + (size_t)row*DD + col) =
                    __halves2half2(__float2half_rn(v00*S2F), __float2half_rn(v01*S2F));
                *(__half2*)(Qh + (size_t)(row+8)*DD + col) =
                    __halves2half2(__float2half_rn(v10*S2F), __float2half_rn(v11*S2F));
            }
        }
}

// ---------------- 1-term attention (base-2), key-split x2, 2 CTAs/SM --------
#define AQ_STRIDE  528                         // 256 half + 16B pad
#define AQS        (128*AQ_STRIDE)             // 67584
#define KB_OFF     AQS
#define KST        (128*80)                    // 32-dim chunk, 128 keys
#define MRG        (KB_OFF + 4*KST)            // 108544
#define SMEM_ATTN  (MRG + 3072)                // 111616 (2 CTAs/SM)

__global__ __launch_bounds__(256, 2) void attn2(const __half* __restrict__ Qh_,
        const __half* __restrict__ yh_)
{
    extern __shared__ __align__(128) char smem[];
    const uint32_t sb = smem_u32(smem);
    const int t = threadIdx.x, lane = t & 31, wid = t >> 5;
    const int wm = wid >> 1, wn = wid & 1;
    const int b = blockIdx.y, q0 = blockIdx.x * 128;
    const int part = blockIdx.z;                 // key half

    const __half* Kb = yh_ + ((size_t)b*NN + part*2048)*DD;
    const __half* Qg = Qh_ + (size_t)(b*NN + q0)*DD;

    // prologue group 0: Q tile (128 rows x 512B) via cp.async
    {
        #pragma unroll
        for (int i = 0; i < 16; i++) {
            int sidx = t*16 + i;                 // 4096 16B chunks
            int row = sidx >> 5, seg = sidx & 31;
            CP16(sb + row*AQ_STRIDE + seg*16, Qg + (size_t)row*DD + seg*8);
        }
        CPC();
    }
    // groups 1..3: K chunks 0..2
    #pragma unroll
    for (int st = 0; st < 3; st++) {
        #pragma unroll
        for (int i = 0; i < 2; i++) {
            int sidx = t*2 + i; int row = sidx >> 2, seg = sidx & 3;
            CP16(sb + KB_OFF + st*KST + row*80 + seg*16,
                 Kb + (size_t)row*DD + st*32 + seg*8);
        }
        CPC();
    }

    float c[2][8][4] = {};
    float rm[4], rs[4]; int ra[4];
    #pragma unroll
    for (int j = 0; j < 4; j++) { rm[j] = -3.0e38f; rs[j] = 0.f; ra[j] = 0; }

    const uint32_t aRowOff = (uint32_t)(wm*32 + (lane&15))*AQ_STRIDE + ((lane>>4)&1)*16;
    const uint32_t bRowOff = (uint32_t)(wn*64 + (lane&7) + ((lane>>3)&1)*8)*80
                           + ((lane>>4)&1)*16;

    // 16 key-tiles x 8 dim-chunks = 128 iterations
    for (int idx = 0; idx < 128; idx++) {
        CPW2();                        // Q + chunk idx resident (<=2 pending)
        __syncthreads();
        if (idx + 3 < 128) {
            int nx = idx + 3, nkt = nx >> 3, nch = nx & 7, nb = nx & 3;
            #pragma unroll
            for (int i = 0; i < 2; i++) {
                int sidx = t*2 + i; int row = sidx >> 2, seg = sidx & 3;
                CP16(sb + KB_OFF + nb*KST + row*80 + seg*16,
                     Kb + (size_t)(nkt*128+row)*DD + nch*32 + seg*8);
            }
            CPC();
        }
        uint32_t aBase = sb + aRowOff + (uint32_t)(idx & 7)*64;
        uint32_t bBase = sb + KB_OFF + (idx & 3)*KST + bRowOff;
        #pragma unroll
        for (int ks = 0; ks < 2; ks++) {
            uint32_t a0,a1,a2,a3,a4,a5,a6,a7;
            ldsm4(aBase + ks*32,                  a0,a1,a2,a3);
            ldsm4(aBase + 16*AQ_STRIDE + ks*32,   a4,a5,a6,a7);
            #pragma unroll
            for (int p = 0; p < 4; p++) {
                uint32_t b0,b1,b2,b3;
                ldsm4(bBase + p*1280 + ks*32, b0,b1,b2,b3);
                mma16816(c[0][2*p+0], a0,a1,a2,a3, b0,b2);
                mma16816(c[0][2*p+1], a0,a1,a2,a3, b1,b3);
                mma16816(c[1][2*p+0], a4,a5,a6,a7, b0,b2);
                mma16816(c[1][2*p+1], a4,a5,a6,a7, b1,b3);
            }
        }

        if ((idx & 7) == 7) {
            int kt = idx >> 3;
            #pragma unroll
            for (int j = 0; j < 4; j++) {
                int mi = j >> 1, hr = (j & 1) * 2;
                float tm = -3.0e38f; int ta = 0;
                #pragma unroll
                for (int ni = 0; ni < 8; ni++) {
                    float v0 = c[mi][ni][hr], v1 = c[mi][ni][hr+1];
                    int col = ni*8 + 2*(lane&3);
                    if (v0 > tm) { tm = v0; ta = col; }
                    if (v1 > tm) { tm = v1; ta = col+1; }
                }
                #pragma unroll
                for (int off = 1; off <= 2; off <<= 1) {
                    float om = __shfl_xor_sync(0xffffffffu, tm, off);
                    int   oa = __shfl_xor_sync(0xffffffffu, ta, off);
                    if (om > tm || (om == tm && oa < ta)) { tm = om; ta = oa; }
                }
                float ts = 0.f;
                #pragma unroll
                for (int ni = 0; ni < 8; ni++) {
                    ts += exp2f(c[mi][ni][hr]   - tm);
                    ts += exp2f(c[mi][ni][hr+1] - tm);
                }
                #pragma unroll
                for (int off = 1; off <= 2; off <<= 1)
                    ts += __shfl_xor_sync(0xffffffffu, ts, off);
                if (tm > rm[j]) {
                    rs[j] = rs[j]*exp2f(rm[j]-tm) + ts;
                    rm[j] = tm;
                    ra[j] = part*2048 + kt*128 + wn*64 + ta;
                } else {
                    rs[j] += ts*exp2f(tm - rm[j]);
                }
            }
            #pragma unroll
            for (int mi = 0; mi < 2; mi++)
                #pragma unroll
                for (int ni = 0; ni < 8; ni++)
                    #pragma unroll
                    for (int r = 0; r < 4; r++) c[mi][ni][r] = 0.f;
        }
    }

    // ---- merge 2 n-halves, write per-half partial stats to global ----
    float* m_arr = (float*)(smem + MRG);           // [256]
    float* s_arr = (float*)(smem + MRG + 1024);    // [256]
    int*   a_arr = (int*)  (smem + MRG + 2048);    // [256]
    if ((lane & 3) == 0) {
        #pragma unroll
        for (int j = 0; j < 4; j++) {
            int row = wm*32 + (j>>1)*16 + (j&1)*8 + (lane>>2);
            m_arr[wn*128 + row] = rm[j];
            s_arr[wn*128 + row] = rs[j];
            a_arr[wn*128 + row] = ra[j];
        }
    }
    __syncthreads();
    if (t < 128) {
        float m0v = m_arr[t], m1v = m_arr[128+t];
        float s0  = s_arr[t], s1  = s_arr[128+t];
        float mm  = fmaxf(m0v, m1v);
        float ss  = s0*exp2f(m0v-mm) + s1*exp2f(m1v-mm);
        int   aa  = (m0v >= m1v) ? a_arr[t] : a_arr[128+t];
        size_t gi = (size_t)part*MTOT + b*NN + q0 + t;
        g_pm[gi] = mm; g_ps[gi] = ss; g_pa[gi] = aa;
    }
}

// ---------------- merge key-halves, classify, write output ------------------
__global__ __launch_bounds__(256) void merge_cls(const float* __restrict__ VP_,
        const float* __restrict__ bp, float* __restrict__ Og_)
{
    __shared__ float p_s[128];
    __shared__ int   f_s[128];
    __shared__ int   a_s[128];
    __shared__ float bp_s[256];
    const int t = threadIdx.x;
    const int base = blockIdx.x * 128;            // global row base

    if (t < 64) ((float4*)bp_s)[t] = ((const float4*)bp)[t];
    if (t < 128) {
        int row = base + t;
        float m0v = g_pm[row], m1v = g_pm[MTOT + row];
        float s0  = g_ps[row], s1  = g_ps[MTOT + row];
        float mm  = fmaxf(m0v, m1v);
        float ss  = s0*exp2f(m0v-mm) + s1*exp2f(m1v-mm);
        int   aa  = (m0v >= m1v) ? g_pa[row] : g_pa[MTOT + row];
        float pt  = 1.0f / ss;
        int cls;
        if (fabsf(pt - 0.6f) < BAND) {
            int slot = atomicAdd(&g_cnt, 1);
            if (slot < MTOT) {
                g_list[slot]   = row;
                g_mval[slot]   = mm;
                g_sumacc[slot] = 0.0;
                g_maxp[slot]   = 0ull;
                cls = 2;
            } else {
                cls = (pt >= 0.6f) ? 1 : 0;
            }
        } else {
            cls = (pt >= 0.6f) ? 1 : 0;
        }
        p_s[t] = pt; f_s[t] = cls; a_s[t] = aa;
    }
    __syncthreads();

    #pragma unroll 4
    for (int i = 0; i < 32; i++) {
        int e4 = t + i*256;
        int row = e4 >> 6, c4 = e4 & 63;
        int cls = f_s[row];
        if (cls == 2) continue;                // finalize writes this row
        int grow = base + row;
        float4 o = ((float4*)bp_s)[c4];
        if (cls == 1) {
            float p = p_s[row];
            int   a = a_s[row];
            int   b = grow >> 12;
            float4 v = ((const float4*)(VP_ + (size_t)(b*NN + a)*DD))[c4];
            o = make_float4(v.x*p + o.x, v.y*p + o.y, v.z*p + o.z, v.w*p + o.w);
        }
        ((float4*)(Og_ + (size_t)grow*DD))[c4] = o;
    }
}

// ---------------- shared-K exact rescue (base-2 stats) ----------------------
#define KSM_STRIDE 260
#define RS_SMEM (64*KSM_STRIDE*4 + 1024 + 64)

__global__ __launch_bounds__(256) void rescue_sum(const float* __restrict__ Qm,
                                                  const float* __restrict__ y)
{
    extern __shared__ __align__(16) char rsm[];
    float* k_sm = (float*)rsm;                         // 64 x 260
    float* q_sm = (float*)(rsm + 64*KSM_STRIDE*4);     // 256
    double* s_acc = (double*)(rsm + 64*KSM_STRIDE*4 + 1024);
    unsigned long long* s_max = (unsigned long long*)(s_acc + 1);

    const int t = threadIdx.x, lane = t & 31;
    const int kb = blockIdx.x, b = blockIdx.y;
    const int key0 = kb * 64;

    const float* Kb = y + ((size_t)b*NN + key0)*DD;
    for (int i = t; i < 64*64; i += 256) {
        int key = i >> 6, c4 = i & 63;
        *(float4*)&k_sm[key*KSM_STRIDE + c4*4] = ((const float4*)Kb)[i];
    }

    int cnt = g_cnt; if (cnt > MTOT) cnt = MTOT;
    const int key  = t >> 2, part = t & 3;
    const float* krow = k_sm + key*KSM_STRIDE + part*64;

    for (int idx = 0; idx < cnt; idx++) {
        int grow = g_list[idx];
        if ((grow >> 12) != b) continue;               // uniform branch
        if (t == 0) { *s_acc = 0.0; *s_max = 0ull; }
        if (t < 64) ((float4*)q_sm)[t] = ((const float4*)(Qm + (size_t)grow*DD))[t];
        __syncthreads();

        const float* qp = q_sm + part*64;
        float acc = 0.f;
        #pragma unroll 16
        for (int d = 0; d < 64; d++) acc += qp[d] * krow[d];
        acc += __shfl_xor_sync(0xffffffffu, acc, 1);
        acc += __shfl_xor_sync(0xffffffffu, acc, 2);
        float s = acc * S2F;                           // base-2 score

        float mval = g_mval[idx];
        double exd = 0.0;
        unsigned long long pk = 0ull;
        if ((t & 3) == 0) {
            exd = (double)exp2f(s - mval);
            uint32_t u = __float_as_uint(s);
            u = (s >= 0.f) ? (u | 0x80000000u) : ~u;
            pk = ((unsigned long long)u << 32) | (uint32_t)(key0 + key);
        }
        #pragma unroll
        for (int off = 4; off <= 16; off <<= 1) {
            exd += __shfl_xor_sync(0xffffffffu, exd, off);
            unsigned long long op = __shfl_xor_sync(0xffffffffu, pk, off);
            if (op > pk) pk = op;
        }
        if (lane == 0) {
            atomicAdd(s_acc, exd);
            atomicMax(s_max, pk);
        }
        __syncthreads();
        if (t == 0) {
            atomicAdd(&g_sumacc[idx], *s_acc);
            atomicMax(&g_maxp[idx], *s_max);
        }
    }
}

// ---------------- finalize band rows ----------------------------------------
__global__ __launch_bounds__(256) void finalize(const float* __restrict__ VP,
        const float* __restrict__ bp, float* __restrict__ O)
{
    int cnt = g_cnt; if (cnt > MTOT) cnt = MTOT;
    const int t = threadIdx.x;
    for (int idx = blockIdx.x; idx < cnt; idx += gridDim.x) {
        int grow = g_list[idx];
        int b = grow >> 12;
        double S = g_sumacc[idx];
        unsigned long long pk = g_maxp[idx];
        uint32_t u = (uint32_t)(pk >> 32);
        int amax = (int)(pk & 0xffffffffu);
        uint32_t ru = (u & 0x80000000u) ? (u & 0x7fffffffu) : ~u;
        float smax = __uint_as_float(ru);
        double p = exp2((double)smax - (double)g_mval[idx]) / S;
        float out;
        if (p >= 0.6) out = (float)p * VP[((size_t)(b*NN) + amax)*DD + t] + bp[t];
        else          out = bp[t];
        O[(size_t)grow*DD + t] = out;
    }
}

// ---------------------------------------------------------------------------
extern "C" void kernel_launch(void* const* d_in, const int* in_sizes, int n_in,
                              void* d_out, int out_size)
{
    const float* x  = (const float*)d_in[0];
    const float* y  = (const float*)d_in[1];
    const float* Wq = (const float*)d_in[2];
    const float* Wk = (const float*)d_in[3];
    const float* Wv = (const float*)d_in[4];
    const float* Wp = (const float*)d_in[5];
    const float* bp = (const float*)d_in[6];
    float* out = (float*)d_out;

    __half *Aaug, *yh, *Wt2, *Qh;
    float *Qm, *VP;
    void* cntp;
    cudaGetSymbolAddress((void**)&Aaug, g_Aaug);
    cudaGetSymbolAddress((void**)&yh,   g_yh);
    cudaGetSymbolAddress((void**)&Qm,   g_Qm);
    cudaGetSymbolAddress((void**)&Qh,   g_Qh);
    cudaGetSymbolAddress((void**)&VP,   g_VP);
    cudaGetSymbolAddress((void**)&Wt2,  g_Wt2);
    cudaGetSymbolAddress(&cntp,         g_cnt);

    cudaFuncSetAttribute(attn2,
                         cudaFuncAttributeMaxDynamicSharedMemorySize, SMEM_ATTN);
    cudaFuncSetAttribute(rescue_sum,
                         cudaFuncAttributeMaxDynamicSharedMemorySize, RS_SMEM);

    cudaMemsetAsync(cntp, 0, sizeof(int));

    prep_xy<<<4096, 256>>>(x, y, Aaug, yh);
    wgemm_qk<<<dim3(4,4), 256>>>(Wq, Wk, Wt2);
    wgemm_vp<<<dim3(4,4), 256>>>(Wv, Wp, Wt2);

    hgemm2<<<dim3(MTOT/128, 4), 256>>>(Aaug, Wt2, Qm, Qh, VP);

    attn2<<<dim3(NN/128, BB, 2), 256, SMEM_ATTN>>>(Qh, yh);
    merge_cls<<<MTOT/128, 256>>>(VP, bp, out);
    rescue_sum<<<dim3(64, BB), 256, RS_SMEM>>>(Qm, y);
    finalize<<<128, 256>>>(VP, bp, out);
}

// round 15
// speedup vs baseline: 1.2413x; 1.0358x over previous
#include <cuda_runtime.h>
#include <cuda_fp16.h>
#include <math.h>
#include <stdint.h>

#define BB 4
#define NN 4096
#define DD 256
#define MTOT (BB*NN)          // 16384
#define KAUG 768              // 3-term split width (projection GEMM)
#define SCALE_F 0.17677669529663689f
#define LOG2E   1.4426950408889634f
#define S2F     (SCALE_F*LOG2E)               // base-2 score scale
#define BAND 4.0e-3f

// ---------------- static device scratch ------------------------------------
__device__ __half g_Aaug[(size_t)MTOT*KAUG];   // x augmented [h|h|l]
__device__ __half g_yh  [(size_t)MTOT*DD];     // y rounded to fp16 (attn K)
__device__ float  g_Qm  [(size_t)MTOT*DD];     // x . (Wq Wk^T)  (exact, for rescue)
__device__ __half g_Qh  [(size_t)MTOT*DD];     // fp16(Qm * SCALE * log2e)
__device__ float  g_VP  [(size_t)MTOT*DD];     // x . (Wv Wp)
__device__ __half g_Wt2 [(size_t)2*DD*KAUG];   // [M ; Wvp] split B-style
__device__ float  g_pm[2*MTOT];                // partial max (base-2) per key-half
__device__ float  g_ps[2*MTOT];                // partial sum exp2(s) (no offset)
__device__ int    g_pa[2*MTOT];                // partial argmax
__device__ int    g_cnt;
__device__ int    g_list[MTOT];
__device__ float  g_mval[MTOT];
__device__ double g_sumacc[MTOT];
__device__ unsigned long long g_maxp[MTOT];

// ---------------- PTX helpers ----------------------------------------------
__device__ __forceinline__ uint32_t smem_u32(const void* p){
    uint32_t a;
    asm("{ .reg .u64 t; cvta.to.shared.u64 t, %1; cvt.u32.u64 %0, t; }" : "=r"(a) : "l"(p));
    return a;
}
__device__ __forceinline__ float ex2(float x){
    float r; asm("ex2.approx.ftz.f32 %0, %1;" : "=f"(r) : "f"(x)); return r;
}
#define CP16(dst, src) \
    asm volatile("cp.async.cg.shared.global [%0], [%1], 16;" :: "r"(dst), "l"(src) : "memory")
#define CPC()  asm volatile("cp.async.commit_group;" ::: "memory")
#define CPW0() asm volatile("cp.async.wait_group 0;" ::: "memory")
#define CPW2() asm volatile("cp.async.wait_group 2;" ::: "memory")

__device__ __forceinline__ void ldsm4(uint32_t a, uint32_t& r0, uint32_t& r1,
                                      uint32_t& r2, uint32_t& r3){
    asm volatile("ldmatrix.sync.aligned.m8n8.x4.shared.b16 {%0,%1,%2,%3}, [%4];"
        : "=r"(r0), "=r"(r1), "=r"(r2), "=r"(r3) : "r"(a));
}
__device__ __forceinline__ void mma16816(float* c,
        uint32_t a0, uint32_t a1, uint32_t a2, uint32_t a3,
        uint32_t b0, uint32_t b1){
    asm volatile("mma.sync.aligned.m16n8k16.row.col.f32.f16.f16.f32 "
        "{%0,%1,%2,%3}, {%4,%5,%6,%7}, {%8,%9}, {%0,%1,%2,%3};"
        : "+f"(c[0]), "+f"(c[1]), "+f"(c[2]), "+f"(c[3])
        : "r"(a0), "r"(a1), "r"(a2), "r"(a3), "r"(b0), "r"(b1));
}

// ---------------- fused input prep: x -> Aaug [h|h|l], y -> fp16 ------------
__global__ void prep_xy(const float* __restrict__ x, const float* __restrict__ y,
                        __half* __restrict__ Aaug, __half* __restrict__ yh)
{
    const size_t totalx = (size_t)MTOT * 64;
    const size_t total  = totalx * 2;
    for (size_t i = (size_t)blockIdx.x*blockDim.x + threadIdx.x; i < total;
         i += (size_t)gridDim.x*blockDim.x) {
        if (i < totalx) {
            size_t row = i >> 6; int c4 = (int)(i & 63);
            float4 v = ((const float4*)x)[i];
            __half h0=__float2half_rn(v.x), h1=__float2half_rn(v.y);
            __half h2=__float2half_rn(v.z), h3=__float2half_rn(v.w);
            __half2 H01=__halves2half2(h0,h1), H23=__halves2half2(h2,h3);
            __half2 L01=__halves2half2(__float2half_rn(v.x-__half2float(h0)),
                                       __float2half_rn(v.y-__half2float(h1)));
            __half2 L23=__halves2half2(__float2half_rn(v.z-__half2float(h2)),
                                       __float2half_rn(v.w-__half2float(h3)));
            __half* base = Aaug + row*KAUG + c4*4;
            ((__half2*)base)[0] = H01; ((__half2*)base)[1] = H23;
            ((__half2*)(base+256))[0] = H01; ((__half2*)(base+256))[1] = H23;
            ((__half2*)(base+512))[0] = L01; ((__half2*)(base+512))[1] = L23;
        } else {
            size_t j = i - totalx;
            float4 v = ((const float4*)y)[j];
            ((__half2*)yh)[j*2]   = __halves2half2(__float2half_rn(v.x), __float2half_rn(v.y));
            ((__half2*)yh)[j*2+1] = __halves2half2(__float2half_rn(v.z), __float2half_rn(v.w));
        }
    }
}

// ---------------- weight GEMMs with split epilogue --------------------------
__global__ __launch_bounds__(256) void wgemm_qk(const float* __restrict__ Wq,
                                                const float* __restrict__ Wk,
                                                __half* __restrict__ Wt2)
{
    __shared__ float As[64][17];
    __shared__ float Ws[16][64];
    const int t  = threadIdx.x;
    const int tx = t & 15, ty = t >> 4;
    const int m0 = blockIdx.x * 64, n0 = blockIdx.y * 64;
    const int lr = t >> 2, lc = (t & 3) * 4;
    float acc[4][4] = {};
    for (int kk = 0; kk < 256; kk += 16) {
        float4 av = *(const float4*)(Wq + (size_t)(m0 + lr) * 256 + kk + lc);
        As[lr][lc+0]=av.x; As[lr][lc+1]=av.y; As[lr][lc+2]=av.z; As[lr][lc+3]=av.w;
        #pragma unroll
        for (int i = 0; i < 4; i++)
            Ws[ty][tx*4+i] = Wk[(size_t)(n0 + tx*4 + i) * 256 + kk + ty];
        __syncthreads();
        #pragma unroll
        for (int c = 0; c < 16; c++) {
            float a0=As[ty*4+0][c], a1=As[ty*4+1][c], a2=As[ty*4+2][c], a3=As[ty*4+3][c];
            float4 w = *(const float4*)&Ws[c][tx*4];
            acc[0][0]+=a0*w.x; acc[0][1]+=a0*w.y; acc[0][2]+=a0*w.z; acc[0][3]+=a0*w.w;
            acc[1][0]+=a1*w.x; acc[1][1]+=a1*w.y; acc[1][2]+=a1*w.z; acc[1][3]+=a1*w.w;
            acc[2][0]+=a2*w.x; acc[2][1]+=a2*w.y; acc[2][2]+=a2*w.z; acc[2][3]+=a2*w.w;
            acc[3][0]+=a3*w.x; acc[3][1]+=a3*w.y; acc[3][2]+=a3*w.z; acc[3][3]+=a3*w.w;
        }
        __syncthreads();
    }
    #pragma unroll
    for (int j2 = 0; j2 < 4; j2++) {
        int i = m0 + ty*4 + j2;
        #pragma unroll
        for (int c = 0; c < 4; c++) {
            int n = n0 + tx*4 + c;
            float v = acc[j2][c];
            __half h = __float2half_rn(v);
            __half l = __float2half_rn(v - __half2float(h));
            __half* dst = Wt2 + (size_t)n*KAUG;
            dst[i] = h; dst[256 + i] = l; dst[512 + i] = h;
        }
    }
}

__global__ __launch_bounds__(256) void wgemm_vp(const float* __restrict__ Wv,
                                                const float* __restrict__ Wp,
                                                __half* __restrict__ Wt2)
{
    __shared__ float As[64][17];
    __shared__ float Ws[16][64];
    const int t  = threadIdx.x;
    const int tx = t & 15, ty = t >> 4;
    const int m0 = blockIdx.x * 64, n0 = blockIdx.y * 64;
    const int lr = t >> 2, lc = (t & 3) * 4;
    float acc[4][4] = {};
    for (int kk = 0; kk < 256; kk += 16) {
        float4 av = *(const float4*)(Wv + (size_t)(m0 + lr) * 256 + kk + lc);
        As[lr][lc+0]=av.x; As[lr][lc+1]=av.y; As[lr][lc+2]=av.z; As[lr][lc+3]=av.w;
        float4 wv = *(const float4*)(Wp + (size_t)(kk + ty) * 256 + n0 + tx * 4);
        *(float4*)&Ws[ty][tx*4] = wv;
        __syncthreads();
        #pragma unroll
        for (int c = 0; c < 16; c++) {
            float a0=As[ty*4+0][c], a1=As[ty*4+1][c], a2=As[ty*4+2][c], a3=As[ty*4+3][c];
            float4 w = *(const float4*)&Ws[c][tx*4];
            acc[0][0]+=a0*w.x; acc[0][1]+=a0*w.y; acc[0][2]+=a0*w.z; acc[0][3]+=a0*w.w;
            acc[1][0]+=a1*w.x; acc[1][1]+=a1*w.y; acc[1][2]+=a1*w.z; acc[1][3]+=a1*w.w;
            acc[2][0]+=a2*w.x; acc[2][1]+=a2*w.y; acc[2][2]+=a2*w.z; acc[2][3]+=a2*w.w;
            acc[3][0]+=a3*w.x; acc[3][1]+=a3*w.y; acc[3][2]+=a3*w.z; acc[3][3]+=a3*w.w;
        }
        __syncthreads();
    }
    #pragma unroll
    for (int j2 = 0; j2 < 4; j2++) {
        int i = m0 + ty*4 + j2;
        #pragma unroll
        for (int c = 0; c < 4; c++) {
            int n = n0 + tx*4 + c;
            float v = acc[j2][c];
            __half h = __float2half_rn(v);
            __half l = __float2half_rn(v - __half2float(h));
            __half* dst = Wt2 + (size_t)(256 + n)*KAUG;
            dst[i] = h; dst[256 + i] = l; dst[512 + i] = h;
        }
    }
}

// ---------------- fused HMMA GEMM: [Qm | VP] = Aaug . Wt2^T -----------------
__global__ __launch_bounds__(256) void hgemm2(const __half* __restrict__ A,
                                              const __half* __restrict__ Bw,
                                              float* __restrict__ Qm,
                                              __half* __restrict__ Qh,
                                              float* __restrict__ VP)
{
    __shared__ __align__(16) char sm[4*10240];
    const uint32_t sb = smem_u32(sm);
    const int t = threadIdx.x, lane = t & 31, wid = t >> 5;
    const int wm = wid >> 1, wn = wid & 1;
    const int m0 = blockIdx.x * 128, n0 = blockIdx.y * 128;
    const bool isQ = (blockIdx.y < 2);
    float* C   = isQ ? Qm : VP;
    const int coff = isQ ? 0 : 256;
    const int NCH = isQ ? 24 : 16;

    float c[2][8][4] = {};
    {
        #pragma unroll
        for (int i = 0; i < 2; i++) {
            int sidx = t*2 + i; int row = sidx >> 2, seg = sidx & 3;
            CP16(sb + row*80 + seg*16,           A  + (size_t)(m0+row)*KAUG + seg*8);
            CP16(sb + 20480 + row*80 + seg*16,   Bw + (size_t)(n0+row)*KAUG + seg*8);
        }
        CPC();
    }
    const uint32_t aRowOff = (uint32_t)(wm*32 + (lane&15))*80 + ((lane>>4)&1)*16;
    const uint32_t bRowOff = (uint32_t)(wn*64 + (lane&7) + ((lane>>3)&1)*8)*80
                           + ((lane>>4)&1)*16;

    for (int ch = 0; ch < NCH; ch++) {
        int buf = ch & 1;
        CPW0();
        __syncthreads();
        if (ch + 1 < NCH) {
            int nb = buf ^ 1;
            #pragma unroll
            for (int i = 0; i < 2; i++) {
                int sidx = t*2 + i; int row = sidx >> 2, seg = sidx & 3;
                CP16(sb + nb*10240 + row*80 + seg*16,
                     A  + (size_t)(m0+row)*KAUG + (ch+1)*32 + seg*8);
                CP16(sb + 20480 + nb*10240 + row*80 + seg*16,
                     Bw + (size_t)(n0+row)*KAUG + (ch+1)*32 + seg*8);
            }
            CPC();
        }
        uint32_t aBase = sb + buf*10240 + aRowOff;
        uint32_t bBase = sb + 20480 + buf*10240 + bRowOff;
        #pragma unroll
        for (int ks = 0; ks < 2; ks++) {
            uint32_t a0,a1,a2,a3,a4,a5,a6,a7;
            ldsm4(aBase + ks*32,            a0,a1,a2,a3);
            ldsm4(aBase + 16*80 + ks*32,    a4,a5,a6,a7);
            #pragma unroll
            for (int p = 0; p < 4; p++) {
                uint32_t b0,b1,b2,b3;
                ldsm4(bBase + p*1280 + ks*32, b0,b1,b2,b3);
                mma16816(c[0][2*p+0], a0,a1,a2,a3, b0,b2);
                mma16816(c[0][2*p+1], a0,a1,a2,a3, b1,b3);
                mma16816(c[1][2*p+0], a4,a5,a6,a7, b0,b2);
                mma16816(c[1][2*p+1], a4,a5,a6,a7, b1,b3);
            }
        }
    }
    #pragma unroll
    for (int mi = 0; mi < 2; mi++)
        #pragma unroll
        for (int ni = 0; ni < 8; ni++) {
            int row = m0 + wm*32 + mi*16 + (lane>>2);
            int col = n0 - coff + wn*64 + ni*8 + 2*(lane&3);
            float v00 = c[mi][ni][0], v01 = c[mi][ni][1];
            float v10 = c[mi][ni][2], v11 = c[mi][ni][3];
            *(float2*)(C + (size_t)row*DD + col)     = make_float2(v00, v01);
            *(float2*)(C + (size_t)(row+8)*DD + col) = make_float2(v10, v11);
            if (isQ) {
                *(__half2*)(Qh + (size_t)row*DD + col) =
                    __halves2half2(__float2half_rn(v00*S2F), __float2half_rn(v01*S2F));
                *(__half2*)(Qh + (size_t)(row+8)*DD + col) =
                    __halves2half2(__float2half_rn(v10*S2F), __float2half_rn(v11*S2F));
            }
        }
}

// ---------------- 1-term attention (base-2, fixed-offset sum) ---------------
#define AQ_STRIDE  528                         // 256 half + 16B pad
#define AQS        (128*AQ_STRIDE)             // 67584
#define KB_OFF     AQS
#define KST        (128*80)                    // 32-dim chunk, 128 keys
#define MRG        (KB_OFF + 4*KST)            // 108544
#define SMEM_ATTN  (MRG + 3072)                // 111616 (2 CTAs/SM)

__global__ __launch_bounds__(256, 2) void attn2(const __half* __restrict__ Qh_,
        const __half* __restrict__ yh_)
{
    extern __shared__ __align__(128) char smem[];
    const uint32_t sb = smem_u32(smem);
    const int t = threadIdx.x, lane = t & 31, wid = t >> 5;
    const int wm = wid >> 1, wn = wid & 1;
    const int b = blockIdx.y, q0 = blockIdx.x * 128;
    const int part = blockIdx.z;                 // key half

    const __half* Kb = yh_ + ((size_t)b*NN + part*2048)*DD;
    const __half* Qg = Qh_ + (size_t)(b*NN + q0)*DD;

    // prologue group 0: Q tile via cp.async
    {
        #pragma unroll
        for (int i = 0; i < 16; i++) {
            int sidx = t*16 + i;
            int row = sidx >> 5, seg = sidx & 31;
            CP16(sb + row*AQ_STRIDE + seg*16, Qg + (size_t)row*DD + seg*8);
        }
        CPC();
    }
    // groups 1..3: K chunks 0..2
    #pragma unroll
    for (int st = 0; st < 3; st++) {
        #pragma unroll
        for (int i = 0; i < 2; i++) {
            int sidx = t*2 + i; int row = sidx >> 2, seg = sidx & 3;
            CP16(sb + KB_OFF + st*KST + row*80 + seg*16,
                 Kb + (size_t)row*DD + st*32 + seg*8);
        }
        CPC();
    }

    float c[2][8][4] = {};
    float rm[4], rs[4]; int ra[4];
    #pragma unroll
    for (int j = 0; j < 4; j++) { rm[j] = -3.0e38f; rs[j] = 0.f; ra[j] = 0; }

    const uint32_t aRowOff = (uint32_t)(wm*32 + (lane&15))*AQ_STRIDE + ((lane>>4)&1)*16;
    const uint32_t bRowOff = (uint32_t)(wn*64 + (lane&7) + ((lane>>3)&1)*8)*80
                           + ((lane>>4)&1)*16;

    for (int idx = 0; idx < 128; idx++) {
        CPW2();
        __syncthreads();
        if (idx + 3 < 128) {
            int nx = idx + 3, nkt = nx >> 3, nch = nx & 7, nb = nx & 3;
            #pragma unroll
            for (int i = 0; i < 2; i++) {
                int sidx = t*2 + i; int row = sidx >> 2, seg = sidx & 3;
                CP16(sb + KB_OFF + nb*KST + row*80 + seg*16,
                     Kb + (size_t)(nkt*128+row)*DD + nch*32 + seg*8);
            }
            CPC();
        }
        uint32_t aBase = sb + aRowOff + (uint32_t)(idx & 7)*64;
        uint32_t bBase = sb + KB_OFF + (idx & 3)*KST + bRowOff;
        #pragma unroll
        for (int ks = 0; ks < 2; ks++) {
            uint32_t a0,a1,a2,a3,a4,a5,a6,a7;
            ldsm4(aBase + ks*32,                  a0,a1,a2,a3);
            ldsm4(aBase + 16*AQ_STRIDE + ks*32,   a4,a5,a6,a7);
            #pragma unroll
            for (int p = 0; p < 4; p++) {
                uint32_t b0,b1,b2,b3;
                ldsm4(bBase + p*1280 + ks*32, b0,b1,b2,b3);
                mma16816(c[0][2*p+0], a0,a1,a2,a3, b0,b2);
                mma16816(c[0][2*p+1], a0,a1,a2,a3, b1,b3);
                mma16816(c[1][2*p+0], a4,a5,a6,a7, b0,b2);
                mma16816(c[1][2*p+1], a4,a5,a6,a7, b1,b3);
            }
        }

        if ((idx & 7) == 7) {
            int kt = idx >> 3;
            #pragma unroll
            for (int j = 0; j < 4; j++) {
                int mi = j >> 1, hr = (j & 1) * 2;
                // tile max: FMNMX tree (no serial guard chain)
                float m01[8];
                #pragma unroll
                for (int ni = 0; ni < 8; ni++)
                    m01[ni] = fmaxf(c[mi][ni][hr], c[mi][ni][hr+1]);
                float tm = fmaxf(fmaxf(fmaxf(m01[0],m01[1]), fmaxf(m01[2],m01[3])),
                                 fmaxf(fmaxf(m01[4],m01[5]), fmaxf(m01[6],m01[7])));
                tm = fmaxf(tm, __shfl_xor_sync(0xffffffffu, tm, 1));
                tm = fmaxf(tm, __shfl_xor_sync(0xffffffffu, tm, 2));
                // fixed-offset sum: 4 independent accumulators
                float s0=0.f, s1=0.f, s2=0.f, s3=0.f;
                #pragma unroll
                for (int ni = 0; ni < 8; ni += 4) {
                    s0 += ex2(c[mi][ni+0][hr]) + ex2(c[mi][ni+0][hr+1]);
                    s1 += ex2(c[mi][ni+1][hr]) + ex2(c[mi][ni+1][hr+1]);
                    s2 += ex2(c[mi][ni+2][hr]) + ex2(c[mi][ni+2][hr+1]);
                    s3 += ex2(c[mi][ni+3][hr]) + ex2(c[mi][ni+3][hr+1]);
                }
                float ts = (s0+s1)+(s2+s3);
                ts += __shfl_xor_sync(0xffffffffu, ts, 1);
                ts += __shfl_xor_sync(0xffffffffu, ts, 2);
                rs[j] += ts;
                // argmax: parallel equality match against tm
                int ta = 0x40000000;
                #pragma unroll
                for (int ni = 0; ni < 8; ni++) {
                    int col = ni*8 + 2*(lane&3);
                    if (c[mi][ni][hr]   == tm && col   < ta) ta = col;
                    if (c[mi][ni][hr+1] == tm && col+1 < ta) ta = col+1;
                }
                ta = min(ta, __shfl_xor_sync(0xffffffffu, ta, 1));
                ta = min(ta, __shfl_xor_sync(0xffffffffu, ta, 2));
                if (tm > rm[j]) {
                    rm[j] = tm;
                    ra[j] = part*2048 + kt*128 + wn*64 + ta;
                }
            }
            #pragma unroll
            for (int mi = 0; mi < 2; mi++)
                #pragma unroll
                for (int ni = 0; ni < 8; ni++)
                    #pragma unroll
                    for (int r = 0; r < 4; r++) c[mi][ni][r] = 0.f;
        }
    }

    // ---- merge 2 n-halves (plain adds now), write partial stats ----
    float* m_arr = (float*)(smem + MRG);           // [256]
    float* s_arr = (float*)(smem + MRG + 1024);    // [256]
    int*   a_arr = (int*)  (smem + MRG + 2048);    // [256]
    if ((lane & 3) == 0) {
        #pragma unroll
        for (int j = 0; j < 4; j++) {
            int row = wm*32 + (j>>1)*16 + (j&1)*8 + (lane>>2);
            m_arr[wn*128 + row] = rm[j];
            s_arr[wn*128 + row] = rs[j];
            a_arr[wn*128 + row] = ra[j];
        }
    }
    __syncthreads();
    if (t < 128) {
        float m0v = m_arr[t], m1v = m_arr[128+t];
        float mm  = fmaxf(m0v, m1v);
        float ss  = s_arr[t] + s_arr[128+t];
        int   aa  = (m0v >= m1v) ? a_arr[t] : a_arr[128+t];
        size_t gi = (size_t)part*MTOT + b*NN + q0 + t;
        g_pm[gi] = mm; g_ps[gi] = ss; g_pa[gi] = aa;
    }
}

// ---------------- merge key-halves, classify, write output ------------------
__global__ __launch_bounds__(256) void merge_cls(const float* __restrict__ VP_,
        const float* __restrict__ bp, float* __restrict__ Og_)
{
    __shared__ float p_s[128];
    __shared__ int   f_s[128];
    __shared__ int   a_s[128];
    __shared__ float bp_s[256];
    const int t = threadIdx.x;
    const int base = blockIdx.x * 128;

    if (t < 64) ((float4*)bp_s)[t] = ((const float4*)bp)[t];
    if (t < 128) {
        int row = base + t;
        float m0v = g_pm[row], m1v = g_pm[MTOT + row];
        float mm  = fmaxf(m0v, m1v);
        float ss  = g_ps[row] + g_ps[MTOT + row];
        int   aa  = (m0v >= m1v) ? g_pa[row] : g_pa[MTOT + row];
        float pt  = ex2(mm) / ss;
        int cls;
        if (fabsf(pt - 0.6f) < BAND) {
            int slot = atomicAdd(&g_cnt, 1);
            if (slot < MTOT) {
                g_list[slot]   = row;
                g_mval[slot]   = mm;
                g_sumacc[slot] = 0.0;
                g_maxp[slot]   = 0ull;
                cls = 2;
            } else {
                cls = (pt >= 0.6f) ? 1 : 0;
            }
        } else {
            cls = (pt >= 0.6f) ? 1 : 0;
        }
        p_s[t] = pt; f_s[t] = cls; a_s[t] = aa;
    }
    __syncthreads();

    #pragma unroll 4
    for (int i = 0; i < 32; i++) {
        int e4 = t + i*256;
        int row = e4 >> 6, c4 = e4 & 63;
        int cls = f_s[row];
        if (cls == 2) continue;                // finalize writes this row
        int grow = base + row;
        float4 o = ((float4*)bp_s)[c4];
        if (cls == 1) {
            float p = p_s[row];
            int   a = a_s[row];
            int   b = grow >> 12;
            float4 v = ((const float4*)(VP_ + (size_t)(b*NN + a)*DD))[c4];
            o = make_float4(v.x*p + o.x, v.y*p + o.y, v.z*p + o.z, v.w*p + o.w);
        }
        ((float4*)(Og_ + (size_t)grow*DD))[c4] = o;
    }
}

// ---------------- shared-K exact rescue (base-2 stats) ----------------------
#define KSM_STRIDE 260
#define RS_SMEM (64*KSM_STRIDE*4 + 1024 + 64)

__global__ __launch_bounds__(256) void rescue_sum(const float* __restrict__ Qm,
                                                  const float* __restrict__ y)
{
    extern __shared__ __align__(16) char rsm[];
    float* k_sm = (float*)rsm;                         // 64 x 260
    float* q_sm = (float*)(rsm + 64*KSM_STRIDE*4);     // 256
    double* s_acc = (double*)(rsm + 64*KSM_STRIDE*4 + 1024);
    unsigned long long* s_max = (unsigned long long*)(s_acc + 1);

    const int t = threadIdx.x, lane = t & 31;
    const int kb = blockIdx.x, b = blockIdx.y;
    const int key0 = kb * 64;

    const float* Kb = y + ((size_t)b*NN + key0)*DD;
    for (int i = t; i < 64*64; i += 256) {
        int key = i >> 6, c4 = i & 63;
        *(float4*)&k_sm[key*KSM_STRIDE + c4*4] = ((const float4*)Kb)[i];
    }

    int cnt = g_cnt; if (cnt > MTOT) cnt = MTOT;
    const int key  = t >> 2, part = t & 3;
    const float* krow = k_sm + key*KSM_STRIDE + part*64;

    for (int idx = 0; idx < cnt; idx++) {
        int grow = g_list[idx];
        if ((grow >> 12) != b) continue;               // uniform branch
        if (t == 0) { *s_acc = 0.0; *s_max = 0ull; }
        if (t < 64) ((float4*)q_sm)[t] = ((const float4*)(Qm + (size_t)grow*DD))[t];
        __syncthreads();

        const float* qp = q_sm + part*64;
        float acc = 0.f;
        #pragma unroll 16
        for (int d = 0; d < 64; d++) acc += qp[d] * krow[d];
        acc += __shfl_xor_sync(0xffffffffu, acc, 1);
        acc += __shfl_xor_sync(0xffffffffu, acc, 2);
        float s = acc * S2F;                           // base-2 score

        float mval = g_mval[idx];
        double exd = 0.0;
        unsigned long long pk = 0ull;
        if ((t & 3) == 0) {
            exd = (double)ex2(s - mval);
            uint32_t u = __float_as_uint(s);
            u = (s >= 0.f) ? (u | 0x80000000u) : ~u;
            pk = ((unsigned long long)u << 32) | (uint32_t)(key0 + key);
        }
        #pragma unroll
        for (int off = 4; off <= 16; off <<= 1) {
            exd += __shfl_xor_sync(0xffffffffu, exd, off);
            unsigned long long op = __shfl_xor_sync(0xffffffffu, pk, off);
            if (op > pk) pk = op;
        }
        if (lane == 0) {
            atomicAdd(s_acc, exd);
            atomicMax(s_max, pk);
        }
        __syncthreads();
        if (t == 0) {
            atomicAdd(&g_sumacc[idx], *s_acc);
            atomicMax(&g_maxp[idx], *s_max);
        }
    }
}

// ---------------- finalize band rows ----------------------------------------
__global__ __launch_bounds__(256) void finalize(const float* __restrict__ VP,
        const float* __restrict__ bp, float* __restrict__ O)
{
    int cnt = g_cnt; if (cnt > MTOT) cnt = MTOT;
    const int t = threadIdx.x;
    for (int idx = blockIdx.x; idx < cnt; idx += gridDim.x) {
        int grow = g_list[idx];
        int b = grow >> 12;
        double S = g_sumacc[idx];
        unsigned long long pk = g_maxp[idx];
        uint32_t u = (uint32_t)(pk >> 32);
        int amax = (int)(pk & 0xffffffffu);
        uint32_t ru = (u & 0x80000000u) ? (u & 0x7fffffffu) : ~u;
        float smax = __uint_as_float(ru);
        double p = exp2((double)smax - (double)g_mval[idx]) / S;
        float out;
        if (p >= 0.6) out = (float)p * VP[((size_t)(b*NN) + amax)*DD + t] + bp[t];
        else          out = bp[t];
        O[(size_t)grow*DD + t] = out;
    }
}

// ---------------------------------------------------------------------------
extern "C" void kernel_launch(void* const* d_in, const int* in_sizes, int n_in,
                              void* d_out, int out_size)
{
    const float* x  = (const float*)d_in[0];
    const float* y  = (const float*)d_in[1];
    const float* Wq = (const float*)d_in[2];
    const float* Wk = (const float*)d_in[3];
    const float* Wv = (const float*)d_in[4];
    const float* Wp = (const float*)d_in[5];
    const float* bp = (const float*)d_in[6];
    float* out = (float*)d_out;

    __half *Aaug, *yh, *Wt2, *Qh;
    float *Qm, *VP;
    void* cntp;
    cudaGetSymbolAddress((void**)&Aaug, g_Aaug);
    cudaGetSymbolAddress((void**)&yh,   g_yh);
    cudaGetSymbolAddress((void**)&Qm,   g_Qm);
    cudaGetSymbolAddress((void**)&Qh,   g_Qh);
    cudaGetSymbolAddress((void**)&VP,   g_VP);
    cudaGetSymbolAddress((void**)&Wt2,  g_Wt2);
    cudaGetSymbolAddress(&cntp,         g_cnt);

    cudaFuncSetAttribute(attn2,
                         cudaFuncAttributeMaxDynamicSharedMemorySize, SMEM_ATTN);
    cudaFuncSetAttribute(rescue_sum,
                         cudaFuncAttributeMaxDynamicSharedMemorySize, RS_SMEM);

    cudaMemsetAsync(cntp, 0, sizeof(int));

    prep_xy<<<4096, 256>>>(x, y, Aaug, yh);
    wgemm_qk<<<dim3(4,4), 256>>>(Wq, Wk, Wt2);
    wgemm_vp<<<dim3(4,4), 256>>>(Wv, Wp, Wt2);

    hgemm2<<<dim3(MTOT/128, 4), 256>>>(Aaug, Wt2, Qm, Qh, VP);

    attn2<<<dim3(NN/128, BB, 2), 256, SMEM_ATTN>>>(Qh, yh);
    merge_cls<<<MTOT/128, 256>>>(VP, bp, out);
    rescue_sum<<<dim3(64, BB), 256, RS_SMEM>>>(Qm, y);
    finalize<<<128, 256>>>(VP, bp, out);
}

// round 16
// speedup vs baseline: 1.2531x; 1.0095x over previous
#include <cuda_runtime.h>
#include <cuda_fp16.h>
#include <math.h>
#include <stdint.h>

#define BB 4
#define NN 4096
#define DD 256
#define MTOT (BB*NN)          // 16384
#define KAUG 768              // B-side 3-term split width
#define AW   512              // A-side [h|l] width
#define SCALE_F 0.17677669529663689f
#define LOG2E   1.4426950408889634f
#define S2F     (SCALE_F*LOG2E)               // base-2 score scale
#define BAND 4.0e-3f

// ---------------- static device scratch ------------------------------------
__device__ __half g_Aaug[(size_t)MTOT*AW];     // x augmented [h|l]
__device__ __half g_yh  [(size_t)MTOT*DD];     // y rounded to fp16 (attn K)
__device__ float  g_Qm  [(size_t)MTOT*DD];     // x . (Wq Wk^T)  (exact, for rescue)
__device__ __half g_Qh  [(size_t)MTOT*DD];     // fp16(Qm * SCALE * log2e)
__device__ float  g_VP  [(size_t)MTOT*DD];     // x . (Wv Wp)
__device__ __half g_Wt2 [(size_t)2*DD*KAUG];   // [M ; Wvp] split B-style
__device__ float  g_pm[2*MTOT];                // partial max (base-2) per key-half
__device__ float  g_ps[2*MTOT];                // partial sum exp2(s) (no offset)
__device__ int    g_pa[2*MTOT];                // partial argmax
__device__ int    g_cnt;
__device__ int    g_list[MTOT];
__device__ float  g_mval[MTOT];
__device__ double g_sumacc[MTOT];
__device__ unsigned long long g_maxp[MTOT];

// ---------------- PTX helpers ----------------------------------------------
__device__ __forceinline__ uint32_t smem_u32(const void* p){
    uint32_t a;
    asm("{ .reg .u64 t; cvta.to.shared.u64 t, %1; cvt.u32.u64 %0, t; }" : "=r"(a) : "l"(p));
    return a;
}
__device__ __forceinline__ float ex2(float x){
    float r; asm("ex2.approx.ftz.f32 %0, %1;" : "=f"(r) : "f"(x)); return r;
}
#define CP16(dst, src) \
    asm volatile("cp.async.cg.shared.global [%0], [%1], 16;" :: "r"(dst), "l"(src) : "memory")
#define CPC()  asm volatile("cp.async.commit_group;" ::: "memory")
#define CPW0() asm volatile("cp.async.wait_group 0;" ::: "memory")
#define CPW2() asm volatile("cp.async.wait_group 2;" ::: "memory")

__device__ __forceinline__ void ldsm4(uint32_t a, uint32_t& r0, uint32_t& r1,
                                      uint32_t& r2, uint32_t& r3){
    asm volatile("ldmatrix.sync.aligned.m8n8.x4.shared.b16 {%0,%1,%2,%3}, [%4];"
        : "=r"(r0), "=r"(r1), "=r"(r2), "=r"(r3) : "r"(a));
}
__device__ __forceinline__ void mma16816(float* c,
        uint32_t a0, uint32_t a1, uint32_t a2, uint32_t a3,
        uint32_t b0, uint32_t b1){
    asm volatile("mma.sync.aligned.m16n8k16.row.col.f32.f16.f16.f32 "
        "{%0,%1,%2,%3}, {%4,%5,%6,%7}, {%8,%9}, {%0,%1,%2,%3};"
        : "+f"(c[0]), "+f"(c[1]), "+f"(c[2]), "+f"(c[3])
        : "r"(a0), "r"(a1), "r"(a2), "r"(a3), "r"(b0), "r"(b1));
}

// ---------------- fused input prep: x -> Aaug [h|l], y -> fp16 --------------
__global__ void prep_xy(const float* __restrict__ x, const float* __restrict__ y,
                        __half* __restrict__ Aaug, __half* __restrict__ yh)
{
    const size_t totalx = (size_t)MTOT * 64;
    const size_t total  = totalx * 2;
    for (size_t i = (size_t)blockIdx.x*blockDim.x + threadIdx.x; i < total;
         i += (size_t)gridDim.x*blockDim.x) {
        if (i < totalx) {
            size_t row = i >> 6; int c4 = (int)(i & 63);
            float4 v = ((const float4*)x)[i];
            __half h0=__float2half_rn(v.x), h1=__float2half_rn(v.y);
            __half h2=__float2half_rn(v.z), h3=__float2half_rn(v.w);
            __half2 H01=__halves2half2(h0,h1), H23=__halves2half2(h2,h3);
            __half2 L01=__halves2half2(__float2half_rn(v.x-__half2float(h0)),
                                       __float2half_rn(v.y-__half2float(h1)));
            __half2 L23=__halves2half2(__float2half_rn(v.z-__half2float(h2)),
                                       __float2half_rn(v.w-__half2float(h3)));
            __half* base = Aaug + row*AW + c4*4;
            ((__half2*)base)[0] = H01; ((__half2*)base)[1] = H23;
            ((__half2*)(base+256))[0] = L01; ((__half2*)(base+256))[1] = L23;
        } else {
            size_t j = i - totalx;
            float4 v = ((const float4*)y)[j];
            ((__half2*)yh)[j*2]   = __halves2half2(__float2half_rn(v.x), __float2half_rn(v.y));
            ((__half2*)yh)[j*2+1] = __halves2half2(__float2half_rn(v.z), __float2half_rn(v.w));
        }
    }
}

// ---------------- weight GEMMs with split epilogue --------------------------
__global__ __launch_bounds__(256) void wgemm_qk(const float* __restrict__ Wq,
                                                const float* __restrict__ Wk,
                                                __half* __restrict__ Wt2)
{
    __shared__ float As[64][17];
    __shared__ float Ws[16][64];
    const int t  = threadIdx.x;
    const int tx = t & 15, ty = t >> 4;
    const int m0 = blockIdx.x * 64, n0 = blockIdx.y * 64;
    const int lr = t >> 2, lc = (t & 3) * 4;
    float acc[4][4] = {};
    for (int kk = 0; kk < 256; kk += 16) {
        float4 av = *(const float4*)(Wq + (size_t)(m0 + lr) * 256 + kk + lc);
        As[lr][lc+0]=av.x; As[lr][lc+1]=av.y; As[lr][lc+2]=av.z; As[lr][lc+3]=av.w;
        #pragma unroll
        for (int i = 0; i < 4; i++)
            Ws[ty][tx*4+i] = Wk[(size_t)(n0 + tx*4 + i) * 256 + kk + ty];
        __syncthreads();
        #pragma unroll
        for (int c = 0; c < 16; c++) {
            float a0=As[ty*4+0][c], a1=As[ty*4+1][c], a2=As[ty*4+2][c], a3=As[ty*4+3][c];
            float4 w = *(const float4*)&Ws[c][tx*4];
            acc[0][0]+=a0*w.x; acc[0][1]+=a0*w.y; acc[0][2]+=a0*w.z; acc[0][3]+=a0*w.w;
            acc[1][0]+=a1*w.x; acc[1][1]+=a1*w.y; acc[1][2]+=a1*w.z; acc[1][3]+=a1*w.w;
            acc[2][0]+=a2*w.x; acc[2][1]+=a2*w.y; acc[2][2]+=a2*w.z; acc[2][3]+=a2*w.w;
            acc[3][0]+=a3*w.x; acc[3][1]+=a3*w.y; acc[3][2]+=a3*w.z; acc[3][3]+=a3*w.w;
        }
        __syncthreads();
    }
    #pragma unroll
    for (int j2 = 0; j2 < 4; j2++) {
        int i = m0 + ty*4 + j2;
        #pragma unroll
        for (int c = 0; c < 4; c++) {
            int n = n0 + tx*4 + c;
            float v = acc[j2][c];
            __half h = __float2half_rn(v);
            __half l = __float2half_rn(v - __half2float(h));
            __half* dst = Wt2 + (size_t)n*KAUG;
            dst[i] = h; dst[256 + i] = l; dst[512 + i] = h;
        }
    }
}

__global__ __launch_bounds__(256) void wgemm_vp(const float* __restrict__ Wv,
                                                const float* __restrict__ Wp,
                                                __half* __restrict__ Wt2)
{
    __shared__ float As[64][17];
    __shared__ float Ws[16][64];
    const int t  = threadIdx.x;
    const int tx = t & 15, ty = t >> 4;
    const int m0 = blockIdx.x * 64, n0 = blockIdx.y * 64;
    const int lr = t >> 2, lc = (t & 3) * 4;
    float acc[4][4] = {};
    for (int kk = 0; kk < 256; kk += 16) {
        float4 av = *(const float4*)(Wv + (size_t)(m0 + lr) * 256 + kk + lc);
        As[lr][lc+0]=av.x; As[lr][lc+1]=av.y; As[lr][lc+2]=av.z; As[lr][lc+3]=av.w;
        float4 wv = *(const float4*)(Wp + (size_t)(kk + ty) * 256 + n0 + tx * 4);
        *(float4*)&Ws[ty][tx*4] = wv;
        __syncthreads();
        #pragma unroll
        for (int c = 0; c < 16; c++) {
            float a0=As[ty*4+0][c], a1=As[ty*4+1][c], a2=As[ty*4+2][c], a3=As[ty*4+3][c];
            float4 w = *(const float4*)&Ws[c][tx*4];
            acc[0][0]+=a0*w.x; acc[0][1]+=a0*w.y; acc[0][2]+=a0*w.z; acc[0][3]+=a0*w.w;
            acc[1][0]+=a1*w.x; acc[1][1]+=a1*w.y; acc[1][2]+=a1*w.z; acc[1][3]+=a1*w.w;
            acc[2][0]+=a2*w.x; acc[2][1]+=a2*w.y; acc[2][2]+=a2*w.z; acc[2][3]+=a2*w.w;
            acc[3][0]+=a3*w.x; acc[3][1]+=a3*w.y; acc[3][2]+=a3*w.z; acc[3][3]+=a3*w.w;
        }
        __syncthreads();
    }
    #pragma unroll
    for (int j2 = 0; j2 < 4; j2++) {
        int i = m0 + ty*4 + j2;
        #pragma unroll
        for (int c = 0; c < 4; c++) {
            int n = n0 + tx*4 + c;
            float v = acc[j2][c];
            __half h = __float2half_rn(v);
            __half l = __float2half_rn(v - __half2float(h));
            __half* dst = Wt2 + (size_t)(256 + n)*KAUG;
            dst[i] = h; dst[256 + i] = l; dst[512 + i] = h;
        }
    }
}

// ---------------- fused HMMA GEMM: [Qm | VP] = Aaug . Wt2^T -----------------
// A is 512-wide [h|l]; chunk k-map: 0-7 -> Ah, 8-15 -> Ah, 16-23 -> Al.
__global__ __launch_bounds__(256) void hgemm2(const __half* __restrict__ A,
                                              const __half* __restrict__ Bw,
                                              float* __restrict__ Qm,
                                              __half* __restrict__ Qh,
                                              float* __restrict__ VP)
{
    __shared__ __align__(16) char sm[4*10240];
    const uint32_t sb = smem_u32(sm);
    const int t = threadIdx.x, lane = t & 31, wid = t >> 5;
    const int wm = wid >> 1, wn = wid & 1;
    const int m0 = blockIdx.x * 128, n0 = blockIdx.y * 128;
    const bool isQ = (blockIdx.y < 2);
    float* C   = isQ ? Qm : VP;
    const int coff = isQ ? 0 : 256;
    const int NCH = isQ ? 24 : 16;

    float c[2][8][4] = {};
    {
        #pragma unroll
        for (int i = 0; i < 2; i++) {
            int sidx = t*2 + i; int row = sidx >> 2, seg = sidx & 3;
            CP16(sb + row*80 + seg*16,           A  + (size_t)(m0+row)*AW + seg*8);
            CP16(sb + 20480 + row*80 + seg*16,   Bw + (size_t)(n0+row)*KAUG + seg*8);
        }
        CPC();
    }
    const uint32_t aRowOff = (uint32_t)(wm*32 + (lane&15))*80 + ((lane>>4)&1)*16;
    const uint32_t bRowOff = (uint32_t)(wn*64 + (lane&7) + ((lane>>3)&1)*8)*80
                           + ((lane>>4)&1)*16;

    for (int ch = 0; ch < NCH; ch++) {
        int buf = ch & 1;
        CPW0();
        __syncthreads();
        if (ch + 1 < NCH) {
            int nc = ch + 1, nb = buf ^ 1;
            int ak = ((nc < 16) ? (nc & 7) : (nc - 8)) * 32;
            int bk = nc * 32;
            #pragma unroll
            for (int i = 0; i < 2; i++) {
                int sidx = t*2 + i; int row = sidx >> 2, seg = sidx & 3;
                CP16(sb + nb*10240 + row*80 + seg*16,
                     A  + (size_t)(m0+row)*AW + ak + seg*8);
                CP16(sb + 20480 + nb*10240 + row*80 + seg*16,
                     Bw + (size_t)(n0+row)*KAUG + bk + seg*8);
            }
            CPC();
        }
        uint32_t aBase = sb + buf*10240 + aRowOff;
        uint32_t bBase = sb + 20480 + buf*10240 + bRowOff;
        #pragma unroll
        for (int ks = 0; ks < 2; ks++) {
            uint32_t a0,a1,a2,a3,a4,a5,a6,a7;
            ldsm4(aBase + ks*32,            a0,a1,a2,a3);
            ldsm4(aBase + 16*80 + ks*32,    a4,a5,a6,a7);
            #pragma unroll
            for (int p = 0; p < 4; p++) {
                uint32_t b0,b1,b2,b3;
                ldsm4(bBase + p*1280 + ks*32, b0,b1,b2,b3);
                mma16816(c[0][2*p+0], a0,a1,a2,a3, b0,b2);
                mma16816(c[0][2*p+1], a0,a1,a2,a3, b1,b3);
                mma16816(c[1][2*p+0], a4,a5,a6,a7, b0,b2);
                mma16816(c[1][2*p+1], a4,a5,a6,a7, b1,b3);
            }
        }
    }
    #pragma unroll
    for (int mi = 0; mi < 2; mi++)
        #pragma unroll
        for (int ni = 0; ni < 8; ni++) {
            int row = m0 + wm*32 + mi*16 + (lane>>2);
            int col = n0 - coff + wn*64 + ni*8 + 2*(lane&3);
            float v00 = c[mi][ni][0], v01 = c[mi][ni][1];
            float v10 = c[mi][ni][2], v11 = c[mi][ni][3];
            *(float2*)(C + (size_t)row*DD + col)     = make_float2(v00, v01);
            *(float2*)(C + (size_t)(row+8)*DD + col) = make_float2(v10, v11);
            if (isQ) {
                *(__half2*)(Qh + (size_t)row*DD + col) =
                    __halves2half2(__float2half_rn(v00*S2F), __float2half_rn(v01*S2F));
                *(__half2*)(Qh + (size_t)(row+8)*DD + col) =
                    __halves2half2(__float2half_rn(v10*S2F), __float2half_rn(v11*S2F));
            }
        }
}

// ---------------- 1-term attention (base-2, fixed-offset sum) ---------------
#define AQ_STRIDE  528                         // 256 half + 16B pad
#define AQS        (128*AQ_STRIDE)             // 67584
#define KB_OFF     AQS
#define KST        (128*80)                    // 32-dim chunk, 128 keys
#define MRG        (KB_OFF + 4*KST)            // 108544
#define SMEM_ATTN  (MRG + 3072)                // 111616 (2 CTAs/SM)

__global__ __launch_bounds__(256, 2) void attn2(const __half* __restrict__ Qh_,
        const __half* __restrict__ yh_)
{
    extern __shared__ __align__(128) char smem[];
    const uint32_t sb = smem_u32(smem);
    const int t = threadIdx.x, lane = t & 31, wid = t >> 5;
    const int wm = wid >> 1, wn = wid & 1;
    const int b = blockIdx.y, q0 = blockIdx.x * 128;
    const int part = blockIdx.z;                 // key half

    const __half* Kb = yh_ + ((size_t)b*NN + part*2048)*DD;
    const __half* Qg = Qh_ + (size_t)(b*NN + q0)*DD;

    // prologue group 0: Q tile via cp.async
    {
        #pragma unroll
        for (int i = 0; i < 16; i++) {
            int sidx = t*16 + i;
            int row = sidx >> 5, seg = sidx & 31;
            CP16(sb + row*AQ_STRIDE + seg*16, Qg + (size_t)row*DD + seg*8);
        }
        CPC();
    }
    // groups 1..3: K chunks 0..2
    #pragma unroll
    for (int st = 0; st < 3; st++) {
        #pragma unroll
        for (int i = 0; i < 2; i++) {
            int sidx = t*2 + i; int row = sidx >> 2, seg = sidx & 3;
            CP16(sb + KB_OFF + st*KST + row*80 + seg*16,
                 Kb + (size_t)row*DD + st*32 + seg*8);
        }
        CPC();
    }

    float c[2][8][4] = {};
    float rm[4], rs[4]; int ra[4];
    #pragma unroll
    for (int j = 0; j < 4; j++) { rm[j] = -3.0e38f; rs[j] = 0.f; ra[j] = 0; }

    const uint32_t aRowOff = (uint32_t)(wm*32 + (lane&15))*AQ_STRIDE + ((lane>>4)&1)*16;
    const uint32_t bRowOff = (uint32_t)(wn*64 + (lane&7) + ((lane>>3)&1)*8)*80
                           + ((lane>>4)&1)*16;

    for (int idx = 0; idx < 128; idx++) {
        CPW2();
        __syncthreads();
        if (idx + 3 < 128) {
            int nx = idx + 3, nkt = nx >> 3, nch = nx & 7, nb = nx & 3;
            #pragma unroll
            for (int i = 0; i < 2; i++) {
                int sidx = t*2 + i; int row = sidx >> 2, seg = sidx & 3;
                CP16(sb + KB_OFF + nb*KST + row*80 + seg*16,
                     Kb + (size_t)(nkt*128+row)*DD + nch*32 + seg*8);
            }
            CPC();
        }
        uint32_t aBase = sb + aRowOff + (uint32_t)(idx & 7)*64;
        uint32_t bBase = sb + KB_OFF + (idx & 3)*KST + bRowOff;
        #pragma unroll
        for (int ks = 0; ks < 2; ks++) {
            uint32_t a0,a1,a2,a3,a4,a5,a6,a7;
            ldsm4(aBase + ks*32,                  a0,a1,a2,a3);
            ldsm4(aBase + 16*AQ_STRIDE + ks*32,   a4,a5,a6,a7);
            #pragma unroll
            for (int p = 0; p < 4; p++) {
                uint32_t b0,b1,b2,b3;
                ldsm4(bBase + p*1280 + ks*32, b0,b1,b2,b3);
                mma16816(c[0][2*p+0], a0,a1,a2,a3, b0,b2);
                mma16816(c[0][2*p+1], a0,a1,a2,a3, b1,b3);
                mma16816(c[1][2*p+0], a4,a5,a6,a7, b0,b2);
                mma16816(c[1][2*p+1], a4,a5,a6,a7, b1,b3);
            }
        }

        if ((idx & 7) == 7) {
            int kt = idx >> 3;
            #pragma unroll
            for (int j = 0; j < 4; j++) {
                int mi = j >> 1, hr = (j & 1) * 2;
                float m01[8];
                #pragma unroll
                for (int ni = 0; ni < 8; ni++)
                    m01[ni] = fmaxf(c[mi][ni][hr], c[mi][ni][hr+1]);
                float tm = fmaxf(fmaxf(fmaxf(m01[0],m01[1]), fmaxf(m01[2],m01[3])),
                                 fmaxf(fmaxf(m01[4],m01[5]), fmaxf(m01[6],m01[7])));
                tm = fmaxf(tm, __shfl_xor_sync(0xffffffffu, tm, 1));
                tm = fmaxf(tm, __shfl_xor_sync(0xffffffffu, tm, 2));
                float s0=0.f, s1=0.f, s2=0.f, s3=0.f;
                #pragma unroll
                for (int ni = 0; ni < 8; ni += 4) {
                    s0 += ex2(c[mi][ni+0][hr]) + ex2(c[mi][ni+0][hr+1]);
                    s1 += ex2(c[mi][ni+1][hr]) + ex2(c[mi][ni+1][hr+1]);
                    s2 += ex2(c[mi][ni+2][hr]) + ex2(c[mi][ni+2][hr+1]);
                    s3 += ex2(c[mi][ni+3][hr]) + ex2(c[mi][ni+3][hr+1]);
                }
                float ts = (s0+s1)+(s2+s3);
                ts += __shfl_xor_sync(0xffffffffu, ts, 1);
                ts += __shfl_xor_sync(0xffffffffu, ts, 2);
                rs[j] += ts;
                int ta = 0x40000000;
                #pragma unroll
                for (int ni = 0; ni < 8; ni++) {
                    int col = ni*8 + 2*(lane&3);
                    if (c[mi][ni][hr]   == tm && col   < ta) ta = col;
                    if (c[mi][ni][hr+1] == tm && col+1 < ta) ta = col+1;
                }
                ta = min(ta, __shfl_xor_sync(0xffffffffu, ta, 1));
                ta = min(ta, __shfl_xor_sync(0xffffffffu, ta, 2));
                if (tm > rm[j]) {
                    rm[j] = tm;
                    ra[j] = part*2048 + kt*128 + wn*64 + ta;
                }
            }
            #pragma unroll
            for (int mi = 0; mi < 2; mi++)
                #pragma unroll
                for (int ni = 0; ni < 8; ni++)
                    #pragma unroll
                    for (int r = 0; r < 4; r++) c[mi][ni][r] = 0.f;
        }
    }

    // ---- merge 2 n-halves, write partial stats ----
    float* m_arr = (float*)(smem + MRG);           // [256]
    float* s_arr = (float*)(smem + MRG + 1024);    // [256]
    int*   a_arr = (int*)  (smem + MRG + 2048);    // [256]
    if ((lane & 3) == 0) {
        #pragma unroll
        for (int j = 0; j < 4; j++) {
            int row = wm*32 + (j>>1)*16 + (j&1)*8 + (lane>>2);
            m_arr[wn*128 + row] = rm[j];
            s_arr[wn*128 + row] = rs[j];
            a_arr[wn*128 + row] = ra[j];
        }
    }
    __syncthreads();
    if (t < 128) {
        float m0v = m_arr[t], m1v = m_arr[128+t];
        float mm  = fmaxf(m0v, m1v);
        float ss  = s_arr[t] + s_arr[128+t];
        int   aa  = (m0v >= m1v) ? a_arr[t] : a_arr[128+t];
        size_t gi = (size_t)part*MTOT + b*NN + q0 + t;
        g_pm[gi] = mm; g_ps[gi] = ss; g_pa[gi] = aa;
    }
}

// ---------------- merge key-halves, classify, write output ------------------
__global__ __launch_bounds__(256) void merge_cls(const float* __restrict__ VP_,
        const float* __restrict__ bp, float* __restrict__ Og_)
{
    __shared__ float p_s[128];
    __shared__ int   f_s[128];
    __shared__ int   a_s[128];
    __shared__ float bp_s[256];
    const int t = threadIdx.x;
    const int base = blockIdx.x * 128;

    if (t < 64) ((float4*)bp_s)[t] = ((const float4*)bp)[t];
    if (t < 128) {
        int row = base + t;
        float m0v = g_pm[row], m1v = g_pm[MTOT + row];
        float mm  = fmaxf(m0v, m1v);
        float ss  = g_ps[row] + g_ps[MTOT + row];
        int   aa  = (m0v >= m1v) ? g_pa[row] : g_pa[MTOT + row];
        float pt  = ex2(mm) / ss;
        int cls;
        if (fabsf(pt - 0.6f) < BAND) {
            int slot = atomicAdd(&g_cnt, 1);
            if (slot < MTOT) {
                g_list[slot]   = row;
                g_mval[slot]   = mm;
                g_sumacc[slot] = 0.0;
                g_maxp[slot]   = 0ull;
                cls = 2;
            } else {
                cls = (pt >= 0.6f) ? 1 : 0;
            }
        } else {
            cls = (pt >= 0.6f) ? 1 : 0;
        }
        p_s[t] = pt; f_s[t] = cls; a_s[t] = aa;
    }
    __syncthreads();

    #pragma unroll 4
    for (int i = 0; i < 32; i++) {
        int e4 = t + i*256;
        int row = e4 >> 6, c4 = e4 & 63;
        int cls = f_s[row];
        if (cls == 2) continue;                // finalize writes this row
        int grow = base + row;
        float4 o = ((float4*)bp_s)[c4];
        if (cls == 1) {
            float p = p_s[row];
            int   a = a_s[row];
            int   b = grow >> 12;
            float4 v = ((const float4*)(VP_ + (size_t)(b*NN + a)*DD))[c4];
            o = make_float4(v.x*p + o.x, v.y*p + o.y, v.z*p + o.z, v.w*p + o.w);
        }
        ((float4*)(Og_ + (size_t)grow*DD))[c4] = o;
    }
}

// ---------------- shared-K exact rescue (base-2 stats, batch early-exit) ----
#define KSM_STRIDE 260
#define RS_SMEM (64*KSM_STRIDE*4 + 1024 + 64)

__global__ __launch_bounds__(256) void rescue_sum(const float* __restrict__ Qm,
                                                  const float* __restrict__ y)
{
    extern __shared__ __align__(16) char rsm[];
    float* k_sm = (float*)rsm;                         // 64 x 260
    float* q_sm = (float*)(rsm + 64*KSM_STRIDE*4);     // 256
    double* s_acc = (double*)(rsm + 64*KSM_STRIDE*4 + 1024);
    unsigned long long* s_max = (unsigned long long*)(s_acc + 1);

    const int t = threadIdx.x, lane = t & 31;
    const int kb = blockIdx.x, b = blockIdx.y;
    const int key0 = kb * 64;

    int cnt = g_cnt; if (cnt > MTOT) cnt = MTOT;
    if (cnt == 0) return;
    // early exit if no band row belongs to this batch
    bool any = false;
    for (int i = 0; i < cnt; i++)
        if ((g_list[i] >> 12) == b) { any = true; break; }
    if (!any) return;

    const float* Kb = y + ((size_t)b*NN + key0)*DD;
    for (int i = t; i < 64*64; i += 256) {
        int key = i >> 6, c4 = i & 63;
        *(float4*)&k_sm[key*KSM_STRIDE + c4*4] = ((const float4*)Kb)[i];
    }

    const int key  = t >> 2, part = t & 3;
    const float* krow = k_sm + key*KSM_STRIDE + part*64;

    for (int idx = 0; idx < cnt; idx++) {
        int grow = g_list[idx];
        if ((grow >> 12) != b) continue;               // uniform branch
        if (t == 0) { *s_acc = 0.0; *s_max = 0ull; }
        if (t < 64) ((float4*)q_sm)[t] = ((const float4*)(Qm + (size_t)grow*DD))[t];
        __syncthreads();

        const float* qp = q_sm + part*64;
        float acc = 0.f;
        #pragma unroll 16
        for (int d = 0; d < 64; d++) acc += qp[d] * krow[d];
        acc += __shfl_xor_sync(0xffffffffu, acc, 1);
        acc += __shfl_xor_sync(0xffffffffu, acc, 2);
        float s = acc * S2F;                           // base-2 score

        float mval = g_mval[idx];
        double exd = 0.0;
        unsigned long long pk = 0ull;
        if ((t & 3) == 0) {
            exd = (double)ex2(s - mval);
            uint32_t u = __float_as_uint(s);
            u = (s >= 0.f) ? (u | 0x80000000u) : ~u;
            pk = ((unsigned long long)u << 32) | (uint32_t)(key0 + key);
        }
        #pragma unroll
        for (int off = 4; off <= 16; off <<= 1) {
            exd += __shfl_xor_sync(0xffffffffu, exd, off);
            unsigned long long op = __shfl_xor_sync(0xffffffffu, pk, off);
            if (op > pk) pk = op;
        }
        if (lane == 0) {
            atomicAdd(s_acc, exd);
            atomicMax(s_max, pk);
        }
        __syncthreads();
        if (t == 0) {
            atomicAdd(&g_sumacc[idx], *s_acc);
            atomicMax(&g_maxp[idx], *s_max);
        }
        __syncthreads();
    }
}

// ---------------- finalize band rows ----------------------------------------
__global__ __launch_bounds__(256) void finalize(const float* __restrict__ VP,
        const float* __restrict__ bp, float* __restrict__ O)
{
    int cnt = g_cnt; if (cnt > MTOT) cnt = MTOT;
    const int t = threadIdx.x;
    for (int idx = blockIdx.x; idx < cnt; idx += gridDim.x) {
        int grow = g_list[idx];
        int b = grow >> 12;
        double S = g_sumacc[idx];
        unsigned long long pk = g_maxp[idx];
        uint32_t u = (uint32_t)(pk >> 32);
        int amax = (int)(pk & 0xffffffffu);
        uint32_t ru = (u & 0x80000000u) ? (u & 0x7fffffffu) : ~u;
        float smax = __uint_as_float(ru);
        double p = exp2((double)smax - (double)g_mval[idx]) / S;
        float out;
        if (p >= 0.6) out = (float)p * VP[((size_t)(b*NN) + amax)*DD + t] + bp[t];
        else          out = bp[t];
        O[(size_t)grow*DD + t] = out;
    }
}

// ---------------------------------------------------------------------------
extern "C" void kernel_launch(void* const* d_in, const int* in_sizes, int n_in,
                              void* d_out, int out_size)
{
    const float* x  = (const float*)d_in[0];
    const float* y  = (const float*)d_in[1];
    const float* Wq = (const float*)d_in[2];
    const float* Wk = (const float*)d_in[3];
    const float* Wv = (const float*)d_in[4];
    const float* Wp = (const float*)d_in[5];
    const float* bp = (const float*)d_in[6];
    float* out = (float*)d_out;

    __half *Aaug, *yh, *Wt2, *Qh;
    float *Qm, *VP;
    void* cntp;
    cudaGetSymbolAddress((void**)&Aaug, g_Aaug);
    cudaGetSymbolAddress((void**)&yh,   g_yh);
    cudaGetSymbolAddress((void**)&Qm,   g_Qm);
    cudaGetSymbolAddress((void**)&Qh,   g_Qh);
    cudaGetSymbolAddress((void**)&VP,   g_VP);
    cudaGetSymbolAddress((void**)&Wt2,  g_Wt2);
    cudaGetSymbolAddress(&cntp,         g_cnt);

    cudaFuncSetAttribute(attn2,
                         cudaFuncAttributeMaxDynamicSharedMemorySize, SMEM_ATTN);
    cudaFuncSetAttribute(rescue_sum,
                         cudaFuncAttributeMaxDynamicSharedMemorySize, RS_SMEM);

    cudaMemsetAsync(cntp, 0, sizeof(int));

    prep_xy<<<2048, 256>>>(x, y, Aaug, yh);
    wgemm_qk<<<dim3(4,4), 256>>>(Wq, Wk, Wt2);
    wgemm_vp<<<dim3(4,4), 256>>>(Wv, Wp, Wt2);

    hgemm2<<<dim3(MTOT/128, 4), 256>>>(Aaug, Wt2, Qm, Qh, VP);

    attn2<<<dim3(NN/128, BB, 2), 256, SMEM_ATTN>>>(Qh, yh);
    merge_cls<<<MTOT/128, 256>>>(VP, bp, out);
    rescue_sum<<<dim3(64, BB), 256, RS_SMEM>>>(Qm, y);
    finalize<<<128, 256>>>(VP, bp, out);
}